// round 9
// baseline (speedup 1.0000x reference)
#include <cuda_runtime.h>
#include <cuda_bf16.h>
#include <math.h>
#include <stdint.h>

// Problem constants
#define BB   2
#define TT   2048
#define DD   1024
#define LL   4
#define HH   16
#define HD   64
#define VV   32000
#define DFF  4096
#define MM   (BB*TT)        // 4096 rows
#define QKVD 3072

typedef unsigned long long u64;

// ---------------------------------------------------------------------------
// Scratch (device globals; allocation is forbidden)
// ---------------------------------------------------------------------------
__device__ float g_x  [MM*DD];
__device__ float g_qkv[MM*QKVD];

// bf16 split activations
__device__ __nv_bfloat16 g_ah[MM*DD],  g_al[MM*DD];    // LN out / attn out
__device__ __nv_bfloat16 g_fh[MM*DFF], g_fl[MM*DFF];   // FFN hidden

// bf16 split transposed weights (B side, [N,K] K-major)
__device__ __nv_bfloat16 g_wqkvh[LL*QKVD*DD], g_wqkvl[LL*QKVD*DD];
__device__ __nv_bfloat16 g_woh  [LL*DD*DD],   g_wol  [LL*DD*DD];
__device__ __nv_bfloat16 g_w1h  [LL*DFF*DD],  g_w1l  [LL*DFF*DD];
__device__ __nv_bfloat16 g_w2h  [LL*DD*DFF],  g_w2l  [LL*DD*DFF];
__device__ __nv_bfloat16 g_wouth[VV*DD],      g_woutl[VV*DD];

// ---------------------------------------------------------------------------
// PTX helpers (sm_80/sm_100 base ISA only; no 'a'-suffix features)
// ---------------------------------------------------------------------------
__device__ __forceinline__ uint32_t smem_u32(const void* p) {
    return (uint32_t)__cvta_generic_to_shared(p);
}
#define CP_ASYNC16(dst, src) \
    asm volatile("cp.async.cg.shared.global [%0], [%1], 16;" :: "r"(dst), "l"(src))
#define CP_COMMIT() asm volatile("cp.async.commit_group;" ::: "memory")
#define CP_WAIT0()  asm volatile("cp.async.wait_group 0;" ::: "memory")
#define CP_WAIT1()  asm volatile("cp.async.wait_group 1;" ::: "memory")

__device__ __forceinline__ void ldmat_x4(uint32_t* r, uint32_t addr) {
    asm volatile("ldmatrix.sync.aligned.m8n8.x4.shared.b16 {%0,%1,%2,%3}, [%4];"
                 : "=r"(r[0]), "=r"(r[1]), "=r"(r[2]), "=r"(r[3]) : "r"(addr));
}
__device__ __forceinline__ void mma16816(float* d, const uint32_t* a,
                                         const uint32_t* b) {
    asm volatile(
        "mma.sync.aligned.m16n8k16.row.col.f32.bf16.bf16.f32 "
        "{%0,%1,%2,%3}, {%4,%5,%6,%7}, {%8,%9}, {%0,%1,%2,%3};"
        : "+f"(d[0]), "+f"(d[1]), "+f"(d[2]), "+f"(d[3])
        : "r"(a[0]), "r"(a[1]), "r"(a[2]), "r"(a[3]), "r"(b[0]), "r"(b[1]));
}

// packed f32x2 (Blackwell base ISA, sm_100+)
__device__ __forceinline__ u64 pack2(float lo, float hi) {
    u64 r; asm("mov.b64 %0, {%1, %2};" : "=l"(r) : "f"(lo), "f"(hi)); return r;
}
__device__ __forceinline__ void unpack2(u64 v, float& lo, float& hi) {
    asm("mov.b64 {%0, %1}, %2;" : "=f"(lo), "=f"(hi) : "l"(v));
}
__device__ __forceinline__ u64 fma2(u64 a, u64 b, u64 c) {
    u64 d; asm("fma.rn.f32x2 %0, %1, %2, %3;" : "=l"(d) : "l"(a), "l"(b), "l"(c));
    return d;
}
__device__ __forceinline__ u64 mul2(u64 a, u64 b) {
    u64 d; asm("mul.rn.f32x2 %0, %1, %2;" : "=l"(d) : "l"(a), "l"(b));
    return d;
}

// ---------------------------------------------------------------------------
// Tensor GEMM: C[M,N] = (Ah+Al)[M,K] @ (Bh+Bl)[N,K]^T  (3xBF16 split)
// CTA tile 128x256, BK=32, 512 threads (2x8 warps, 64x32 warp tile),
// 2-stage cp.async pipeline, HOISTED fragments (12 ldmat / k16 / warp).
// MODE: bit0 +bias[n], bit1 +res[m,n], bit2 relu, bit3 write bf16 hi/lo split
// SWAPG: bm = blockIdx.x (M-fast rasterization; for huge-N logits GEMM)
// ---------------------------------------------------------------------------
#define TM 128
#define TN 256
#define BK 32
#define NTHR 512
#define SA 40                       // padded row stride (elements)
#define A_ELE (TM*SA)
#define B_ELE (TN*SA)
#define A_BYT (A_ELE*2)             // 10240
#define B_BYT (B_ELE*2)             // 20480
#define STAGE_BYT (2*A_BYT + 2*B_BYT)   // 61440
#define GEMM_SMEM (2*STAGE_BYT)         // 122880

__device__ __forceinline__ void load_tile(uint32_t sdst, const __nv_bfloat16* g,
                                          int K, int k0, int rows4, int tid) {
    for (int i = tid; i < rows4; i += NTHR) {
        int r = i >> 2, gg = i & 3;
        CP_ASYNC16(sdst + (uint32_t)(r * 80 + gg * 16),
                   (const void*)(g + (size_t)r * K + k0 + gg * 8));
    }
}
__device__ __forceinline__ void load_chunk(uint32_t sb,
    const __nv_bfloat16* gAh, const __nv_bfloat16* gAl,
    const __nv_bfloat16* gBh, const __nv_bfloat16* gBl,
    int K, int k0, int tid) {
    load_tile(sb,                   gAh, K, k0, TM*4, tid);
    load_tile(sb + A_BYT,           gAl, K, k0, TM*4, tid);
    load_tile(sb + 2*A_BYT,         gBh, K, k0, TN*4, tid);
    load_tile(sb + 2*A_BYT + B_BYT, gBl, K, k0, TN*4, tid);
}

template<int MODE, bool SWAPG>
__global__ void __launch_bounds__(NTHR) tc_gemm(
    int M, int N, int K,
    const __nv_bfloat16* __restrict__ Ah, const __nv_bfloat16* __restrict__ Al,
    const __nv_bfloat16* __restrict__ Bh, const __nv_bfloat16* __restrict__ Bl,
    const float* __restrict__ bias, const float* __restrict__ res,
    float* __restrict__ C, __nv_bfloat16* __restrict__ Ch,
    __nv_bfloat16* __restrict__ Cl)
{
    extern __shared__ __nv_bfloat16 sm[];
    uint32_t sbase = smem_u32(sm);
    int tid = threadIdx.x;
    int bm = SWAPG ? blockIdx.x : blockIdx.y;
    int bn = SWAPG ? blockIdx.y : blockIdx.x;
    int warp = tid >> 5, lane = tid & 31;
    int wm = warp & 1, wn = warp >> 1;          // warp grid 2 x 8, tile 64x32

    const __nv_bfloat16* gAh = Ah + (size_t)bm * TM * K;
    const __nv_bfloat16* gAl = Al + (size_t)bm * TM * K;
    const __nv_bfloat16* gBh = Bh + (size_t)bn * TN * K;
    const __nv_bfloat16* gBl = Bl + (size_t)bn * TN * K;

    float acc[4][4][4];
    #pragma unroll
    for (int i = 0; i < 4; i++)
        #pragma unroll
        for (int j = 0; j < 4; j++)
            #pragma unroll
            for (int u = 0; u < 4; u++) acc[i][j][u] = 0.f;

    // ldmatrix lane geometry (shared by A and B)
    int mat = lane >> 3;
    int row_off = (mat & 1) * 8 + (lane & 7);
    int kblk_off = (mat >> 1) * 8;

    const int NC = K / BK;

    // prologue: chunk 0 -> stage 0
    load_chunk(sbase, gAh, gAl, gBh, gBl, K, 0, tid);
    CP_COMMIT();

    for (int c = 0; c < NC; c++) {
        int s = c & 1;
        if (c + 1 < NC) {
            load_chunk(sbase + (uint32_t)((s ^ 1) * STAGE_BYT),
                       gAh, gAl, gBh, gBl, K, (c + 1) * BK, tid);
            CP_COMMIT();
            CP_WAIT1();
        } else {
            CP_WAIT0();
        }
        __syncthreads();

        uint32_t stg = sbase + (uint32_t)(s * STAGE_BYT);
        uint32_t Ash = stg, Asl = stg + A_BYT;
        uint32_t Bsh = stg + 2*A_BYT, Bsl = stg + 2*A_BYT + B_BYT;

        #pragma unroll
        for (int ks = 0; ks < 2; ks++) {
            int k0 = ks * 16 + kblk_off;
            uint32_t af[4][4], bh[2][4], bl[2][4];
            #pragma unroll
            for (int mt = 0; mt < 4; mt++) {
                int r = wm * 64 + mt * 16 + row_off;
                ldmat_x4(af[mt], Ash + (uint32_t)((r * SA + k0) * 2));
            }
            #pragma unroll
            for (int ng = 0; ng < 2; ng++) {
                int r = wn * 32 + ng * 16 + row_off;
                ldmat_x4(bh[ng], Bsh + (uint32_t)((r * SA + k0) * 2));
            }
            #pragma unroll
            for (int ng = 0; ng < 2; ng++) {
                int r = wn * 32 + ng * 16 + row_off;
                ldmat_x4(bl[ng], Bsl + (uint32_t)((r * SA + k0) * 2));
            }
            // Ah * Bh
            #pragma unroll
            for (int mt = 0; mt < 4; mt++)
                #pragma unroll
                for (int nt = 0; nt < 4; nt++) {
                    uint32_t bb[2] = { bh[nt >> 1][nt & 1], bh[nt >> 1][2 + (nt & 1)] };
                    mma16816(acc[mt][nt], af[mt], bb);
                }
            // Ah * Bl
            #pragma unroll
            for (int mt = 0; mt < 4; mt++)
                #pragma unroll
                for (int nt = 0; nt < 4; nt++) {
                    uint32_t bb[2] = { bl[nt >> 1][nt & 1], bl[nt >> 1][2 + (nt & 1)] };
                    mma16816(acc[mt][nt], af[mt], bb);
                }
            // Al * Bh (reuse af registers)
            #pragma unroll
            for (int mt = 0; mt < 4; mt++) {
                int r = wm * 64 + mt * 16 + row_off;
                ldmat_x4(af[mt], Asl + (uint32_t)((r * SA + k0) * 2));
            }
            #pragma unroll
            for (int mt = 0; mt < 4; mt++)
                #pragma unroll
                for (int nt = 0; nt < 4; nt++) {
                    uint32_t bb[2] = { bh[nt >> 1][nt & 1], bh[nt >> 1][2 + (nt & 1)] };
                    mma16816(acc[mt][nt], af[mt], bb);
                }
        }
        __syncthreads();
    }

    // epilogue (compile-time MODE)
    int qr = lane >> 2, qc = (lane & 3) * 2;
    #pragma unroll
    for (int mt = 0; mt < 4; mt++) {
        #pragma unroll
        for (int half = 0; half < 2; half++) {
            int grow = bm * TM + wm * 64 + mt * 16 + half * 8 + qr;
            size_t rowo = (size_t)grow * N;
            #pragma unroll
            for (int nt = 0; nt < 4; nt++) {
                int gcol = bn * TN + wn * 32 + nt * 8 + qc;
                float v0 = acc[mt][nt][half * 2 + 0];
                float v1 = acc[mt][nt][half * 2 + 1];
                if (MODE & 1) { v0 += bias[gcol]; v1 += bias[gcol + 1]; }
                if (MODE & 2) {
                    const float2 r2 = *(const float2*)(res + rowo + gcol);
                    v0 += r2.x; v1 += r2.y;
                }
                if (MODE & 4) { v0 = fmaxf(v0, 0.f); v1 = fmaxf(v1, 0.f); }
                if (MODE & 8) {
                    __nv_bfloat16 h0 = __float2bfloat16(v0);
                    __nv_bfloat16 h1 = __float2bfloat16(v1);
                    __nv_bfloat162 hp; hp.x = h0; hp.y = h1;
                    __nv_bfloat162 lp;
                    lp.x = __float2bfloat16(v0 - __bfloat162float(h0));
                    lp.y = __float2bfloat16(v1 - __bfloat162float(h1));
                    *(__nv_bfloat162*)(Ch + rowo + gcol) = hp;
                    *(__nv_bfloat162*)(Cl + rowo + gcol) = lp;
                } else {
                    float2 o2; o2.x = v0; o2.y = v1;
                    *(float2*)(C + rowo + gcol) = o2;
                }
            }
        }
    }
}

// ---------------------------------------------------------------------------
// Weight transpose + split: W[K,N] fp32 -> Bt{h,l}[N,K] bf16 (4 k-tiles/block)
// ---------------------------------------------------------------------------
__device__ __forceinline__ void tsplit_body(
    const float* __restrict__ W, __nv_bfloat16* __restrict__ Bh,
    __nv_bfloat16* __restrict__ Bl, int K, int N, float (*t)[33])
{
    int n0 = blockIdx.x * 32;
    int tx = threadIdx.x & 31, ty = threadIdx.x >> 5;
    #pragma unroll
    for (int kt = 0; kt < 4; kt++) {
        int k0 = (blockIdx.y * 4 + kt) * 32;
        #pragma unroll
        for (int i = 0; i < 32; i += 8)
            t[ty + i][tx] = W[(size_t)(k0 + ty + i) * N + n0 + tx];
        __syncthreads();
        #pragma unroll
        for (int i = 0; i < 32; i += 8) {
            float v = t[tx][ty + i];
            __nv_bfloat16 hi = __float2bfloat16(v);
            size_t o = (size_t)(n0 + ty + i) * K + k0 + tx;
            Bh[o] = hi;
            Bl[o] = __float2bfloat16(v - __bfloat162float(hi));
        }
        __syncthreads();
    }
}

__global__ __launch_bounds__(256) void transpose_split_kernel(
    const float* __restrict__ W, __nv_bfloat16* __restrict__ Bh,
    __nv_bfloat16* __restrict__ Bl, int K, int N)
{
    __shared__ float t[32][33];
    tsplit_body(W, Bh, Bl, K, N, t);
}

// Fused QKV weight prep: blockIdx.z picks Wq/Wk/Wv (one launch per layer)
__global__ __launch_bounds__(256) void transpose_split_qkv_kernel(
    const float* __restrict__ Wq, const float* __restrict__ Wk,
    const float* __restrict__ Wv, __nv_bfloat16* __restrict__ Bh,
    __nv_bfloat16* __restrict__ Bl)
{
    __shared__ float t[32][33];
    int z = blockIdx.z;
    const float* W = (z == 0) ? Wq : (z == 1) ? Wk : Wv;
    size_t off = (size_t)z * DD * DD;
    tsplit_body(W, Bh + off, Bl + off, DD, DD, t);
}

// ---------------------------------------------------------------------------
// Embedding
// ---------------------------------------------------------------------------
__global__ __launch_bounds__(256) void embed_kernel(
    const int* __restrict__ ctx, const float* __restrict__ tok,
    const float* __restrict__ pos, float* __restrict__ x)
{
    int idx = blockIdx.x * 256 + threadIdx.x;
    int d  = idx & (DD - 1);
    int bt = idx >> 10;
    int t  = bt & (TT - 1);
    int v  = ctx[bt];
    x[idx] = tok[(size_t)v * DD + d] + pos[(size_t)t * DD + d];
}

// ---------------------------------------------------------------------------
// LayerNorm fused with bf16 hi/lo split output
// ---------------------------------------------------------------------------
__global__ __launch_bounds__(256) void ln_split_kernel(
    const float* __restrict__ x, const float* __restrict__ s,
    const float* __restrict__ b, __nv_bfloat16* __restrict__ yh,
    __nv_bfloat16* __restrict__ yl)
{
    int row = blockIdx.x;
    const float* xr = x + (size_t)row * DD;
    int tid = threadIdx.x;

    float v0 = xr[tid], v1 = xr[tid+256], v2 = xr[tid+512], v3 = xr[tid+768];
    float sum = v0+v1+v2+v3;
    float sq  = v0*v0+v1*v1+v2*v2+v3*v3;
    #pragma unroll
    for (int o = 16; o > 0; o >>= 1) {
        sum += __shfl_xor_sync(0xFFFFFFFFu, sum, o);
        sq  += __shfl_xor_sync(0xFFFFFFFFu, sq,  o);
    }
    __shared__ float ssum[8], ssq[8], red[2];
    if ((tid & 31) == 0) { ssum[tid>>5] = sum; ssq[tid>>5] = sq; }
    __syncthreads();
    if (tid < 32) {
        float a = (tid < 8) ? ssum[tid] : 0.f;
        float c = (tid < 8) ? ssq[tid]  : 0.f;
        #pragma unroll
        for (int o = 4; o > 0; o >>= 1) {
            a += __shfl_xor_sync(0xFFFFFFFFu, a, o);
            c += __shfl_xor_sync(0xFFFFFFFFu, c, o);
        }
        if (tid == 0) { red[0] = a; red[1] = c; }
    }
    __syncthreads();
    float mean = red[0] * (1.f/DD);
    float var  = red[1] * (1.f/DD) - mean*mean;
    float inv  = rsqrtf(var + 1e-5f);
    #pragma unroll
    for (int i = 0; i < 4; i++) {
        int c = tid + i*256;
        float val = (xr[c] - mean) * inv * s[c] + b[c];
        __nv_bfloat16 hi = __float2bfloat16(val);
        size_t o = (size_t)row * DD + c;
        yh[o] = hi;
        yl[o] = __float2bfloat16(val - __bfloat162float(hi));
    }
}

// ---------------------------------------------------------------------------
// Flash attention (causal), QKV packed [M,3072]; writes bf16 hi/lo [M,1024]
// Packed f32x2 math (FFMA2) in QK and PV inner loops.
// ---------------------------------------------------------------------------
__global__ __launch_bounds__(128) void attn_kernel(
    const float* __restrict__ QKV, __nv_bfloat16* __restrict__ Oh,
    __nv_bfloat16* __restrict__ Ol)
{
    int qt = blockIdx.x, h = blockIdx.y, b = blockIdx.z;
    int tid = threadIdx.x;
    int q_idx = qt * 128 + tid;

    const float* qp = QKV + ((size_t)(b*TT) + q_idx) * QKVD + h * HD;

    u64 q2[32];
    #pragma unroll
    for (int c = 0; c < 16; c++) {
        float4 t4 = *(const float4*)(qp + c*4);
        q2[2*c+0] = pack2(t4.x * 0.125f, t4.y * 0.125f);
        q2[2*c+1] = pack2(t4.z * 0.125f, t4.w * 0.125f);
    }
    u64 o2[32];
    #pragma unroll
    for (int d = 0; d < 32; d++) o2[d] = 0ULL;
    float m = -1e30f, lsum = 0.f;

    __shared__ float4 Ks[16][16];
    __shared__ float4 Vs[16][16];

    int kend = qt * 128 + 128;
    for (int k0 = 0; k0 < kend; k0 += 16) {
        __syncthreads();
        #pragma unroll
        for (int i = 0; i < 2; i++) {
            int idx = tid + i*128;
            int r = idx >> 4, c = idx & 15;
            size_t rb = ((size_t)(b*TT) + k0 + r) * QKVD + h * HD + c*4;
            Ks[r][c] = *(const float4*)(QKV + rb + DD);
            Vs[r][c] = *(const float4*)(QKV + rb + 2*DD);
        }
        __syncthreads();

        float s[16];
        #pragma unroll
        for (int j = 0; j < 16; j++) {
            const u64* kk = (const u64*)&Ks[j][0];
            u64 s2 = 0ULL;
            #pragma unroll
            for (int c = 0; c < 32; c++) s2 = fma2(q2[c], kk[c], s2);
            float lo, hi; unpack2(s2, lo, hi);
            s[j] = (k0 + j <= q_idx) ? (lo + hi) : -1e30f;
        }
        float mt = m;
        #pragma unroll
        for (int j = 0; j < 16; j++) mt = fmaxf(mt, s[j]);
        float corr = __expf(m - mt);
        m = mt;
        lsum *= corr;
        u64 corr2 = pack2(corr, corr);
        #pragma unroll
        for (int d = 0; d < 32; d++) o2[d] = mul2(o2[d], corr2);

        #pragma unroll
        for (int j = 0; j < 16; j++) {
            float p = __expf(s[j] - m);
            lsum += p;
            u64 p2 = pack2(p, p);
            const u64* vv = (const u64*)&Vs[j][0];
            #pragma unroll
            for (int c = 0; c < 32; c++) o2[c] = fma2(p2, vv[c], o2[c]);
        }
    }

    float inv = 1.f / lsum;
    size_t ob_off = ((size_t)(b*TT) + q_idx) * DD + h * HD;
    #pragma unroll
    for (int c = 0; c < 32; c++) {
        float u0, u1; unpack2(o2[c], u0, u1);
        u0 *= inv; u1 *= inv;
        __nv_bfloat16 h0 = __float2bfloat16(u0);
        __nv_bfloat16 h1 = __float2bfloat16(u1);
        __nv_bfloat162 hp; hp.x = h0; hp.y = h1;
        __nv_bfloat162 lp;
        lp.x = __float2bfloat16(u0 - __bfloat162float(h0));
        lp.y = __float2bfloat16(u1 - __bfloat162float(h1));
        *(__nv_bfloat162*)(Oh + ob_off + 2*c) = hp;
        *(__nv_bfloat162*)(Ol + ob_off + 2*c) = lp;
    }
}

// ---------------------------------------------------------------------------
// Host orchestration
// ---------------------------------------------------------------------------
template<int MODE, bool SWAPG>
static void launch_gemm(const __nv_bfloat16* Ah, const __nv_bfloat16* Al,
                        const __nv_bfloat16* Bh, const __nv_bfloat16* Bl,
                        const float* bias, const float* res, float* C,
                        __nv_bfloat16* Ch, __nv_bfloat16* Cl,
                        int M, int N, int K)
{
    dim3 grid = SWAPG ? dim3(M / TM, N / TN) : dim3(N / TN, M / TM);
    tc_gemm<MODE, SWAPG><<<grid, NTHR, GEMM_SMEM>>>(M, N, K, Ah, Al, Bh, Bl,
                                                    bias, res, C, Ch, Cl);
}

static void launch_tsplit(const float* W, __nv_bfloat16* Bh, __nv_bfloat16* Bl,
                          int K, int N)
{
    dim3 grid(N / 32, K / 128);
    transpose_split_kernel<<<grid, 256>>>(W, Bh, Bl, K, N);
}

extern "C" void kernel_launch(void* const* d_in, const int* in_sizes, int n_in,
                              void* d_out, int out_size)
{
    const int*   ctx  = (const int*)  d_in[0];
    const float* tok  = (const float*)d_in[1];
    const float* pos  = (const float*)d_in[2];
    const float* Wq   = (const float*)d_in[3];
    const float* Wk   = (const float*)d_in[4];
    const float* Wv   = (const float*)d_in[5];
    const float* Wo   = (const float*)d_in[6];
    const float* bo   = (const float*)d_in[7];
    const float* ln1s = (const float*)d_in[8];
    const float* ln1b = (const float*)d_in[9];
    const float* W1   = (const float*)d_in[10];
    const float* b1   = (const float*)d_in[11];
    const float* W2   = (const float*)d_in[12];
    const float* b2   = (const float*)d_in[13];
    const float* ln2s = (const float*)d_in[14];
    const float* ln2b = (const float*)d_in[15];
    const float* lnfs = (const float*)d_in[16];
    const float* lnfb = (const float*)d_in[17];
    const float* Wout = (const float*)d_in[18];
    const float* bout = (const float*)d_in[19];
    float* out = (float*)d_out;

    // smem opt-in for all tc_gemm instantiations (unconditional; no static state)
    cudaFuncSetAttribute(tc_gemm<0,false>,  cudaFuncAttributeMaxDynamicSharedMemorySize, GEMM_SMEM);
    cudaFuncSetAttribute(tc_gemm<3,false>,  cudaFuncAttributeMaxDynamicSharedMemorySize, GEMM_SMEM);
    cudaFuncSetAttribute(tc_gemm<13,false>, cudaFuncAttributeMaxDynamicSharedMemorySize, GEMM_SMEM);
    cudaFuncSetAttribute(tc_gemm<1,true>,   cudaFuncAttributeMaxDynamicSharedMemorySize, GEMM_SMEM);

    float *x, *qkv;
    __nv_bfloat16 *ah, *al, *fh, *fl;
    __nv_bfloat16 *wqkvh, *wqkvl, *woh, *wol, *w1h, *w1l, *w2h, *w2l, *wouth, *woutl;
    cudaGetSymbolAddress((void**)&x,    g_x);
    cudaGetSymbolAddress((void**)&qkv,  g_qkv);
    cudaGetSymbolAddress((void**)&ah,   g_ah);
    cudaGetSymbolAddress((void**)&al,   g_al);
    cudaGetSymbolAddress((void**)&fh,   g_fh);
    cudaGetSymbolAddress((void**)&fl,   g_fl);
    cudaGetSymbolAddress((void**)&wqkvh,g_wqkvh);
    cudaGetSymbolAddress((void**)&wqkvl,g_wqkvl);
    cudaGetSymbolAddress((void**)&woh,  g_woh);
    cudaGetSymbolAddress((void**)&wol,  g_wol);
    cudaGetSymbolAddress((void**)&w1h,  g_w1h);
    cudaGetSymbolAddress((void**)&w1l,  g_w1l);
    cudaGetSymbolAddress((void**)&w2h,  g_w2h);
    cudaGetSymbolAddress((void**)&w2l,  g_w2l);
    cudaGetSymbolAddress((void**)&wouth,g_wouth);
    cudaGetSymbolAddress((void**)&woutl,g_woutl);

    // Stream index 0: fused layer-0 QKV weight prep (one launch)
    {
        dim3 grid(DD / 32, DD / 128, 3);
        transpose_split_qkv_kernel<<<grid, 256>>>(Wq, Wk, Wv, wqkvh, wqkvl);
    }
    // Index 1: embedding
    embed_kernel<<<(MM*DD)/256, 256>>>(ctx, tok, pos, x);
    // Index 2: LN1 (layer 0)
    ln_split_kernel<<<MM, 256>>>(x, ln1s, ln1b, ah, al);
    // Index 3: layer-0 QKV GEMM  (harness offset +2 -> ncu global index 5)
    launch_gemm<0, false>(ah, al, wqkvh, wqkvl, nullptr, nullptr, qkv,
                          nullptr, nullptr, MM, QKVD, DD);

    // Remaining weight prep
    for (int l = 0; l < LL; l++) {
        size_t qo = (size_t)l * QKVD * DD;
        if (l > 0) {
            dim3 grid(DD / 32, DD / 128, 3);
            transpose_split_qkv_kernel<<<grid, 256>>>(
                Wq + (size_t)l*DD*DD, Wk + (size_t)l*DD*DD, Wv + (size_t)l*DD*DD,
                wqkvh + qo, wqkvl + qo);
        }
        launch_tsplit(Wo + (size_t)l*DD*DD,  woh + (size_t)l*DD*DD,  wol + (size_t)l*DD*DD,  DD, DD);
        launch_tsplit(W1 + (size_t)l*DD*DFF, w1h + (size_t)l*DFF*DD, w1l + (size_t)l*DFF*DD, DD, DFF);
        launch_tsplit(W2 + (size_t)l*DFF*DD, w2h + (size_t)l*DD*DFF, w2l + (size_t)l*DD*DFF, DFF, DD);
    }
    launch_tsplit(Wout, wouth, woutl, DD, VV);

    for (int l = 0; l < LL; l++) {
        const __nv_bfloat16* lwqh = wqkvh + (size_t)l*QKVD*DD;
        const __nv_bfloat16* lwql = wqkvl + (size_t)l*QKVD*DD;
        const __nv_bfloat16* lwoh = woh + (size_t)l*DD*DD;
        const __nv_bfloat16* lwol = wol + (size_t)l*DD*DD;
        const __nv_bfloat16* lw1h = w1h + (size_t)l*DFF*DD;
        const __nv_bfloat16* lw1l = w1l + (size_t)l*DFF*DD;
        const __nv_bfloat16* lw2h = w2h + (size_t)l*DD*DFF;
        const __nv_bfloat16* lw2l = w2l + (size_t)l*DD*DFF;

        if (l > 0) {
            ln_split_kernel<<<MM, 256>>>(x, ln1s + l*DD, ln1b + l*DD, ah, al);
            launch_gemm<0, false>(ah, al, lwqh, lwql, nullptr, nullptr, qkv,
                                  nullptr, nullptr, MM, QKVD, DD);
        }

        // attention -> ah/al (bf16 split)
        {
            dim3 grid(TT/128, HH, BB);
            attn_kernel<<<grid, 128>>>(qkv, ah, al);
        }

        // x = x + att @ Wo + bo
        launch_gemm<3, false>(ah, al, lwoh, lwol, bo + l*DD, x, x,
                              nullptr, nullptr, MM, DD, DD);

        // ah/al = split(LN2(x)); fh/fl = split(relu(ah @ W1 + b1))
        ln_split_kernel<<<MM, 256>>>(x, ln2s + l*DD, ln2b + l*DD, ah, al);
        launch_gemm<13, false>(ah, al, lw1h, lw1l, b1 + l*DFF, nullptr, nullptr,
                               fh, fl, MM, DFF, DD);

        // x = x + fh @ W2 + b2
        launch_gemm<3, false>(fh, fl, lw2h, lw2l, b2 + l*DD, x, x,
                              nullptr, nullptr, MM, DD, DFF);
    }

    // final LN + logits (M-fast rasterization: stream 131MB B once)
    ln_split_kernel<<<MM, 256>>>(x, lnfs, lnfb, ah, al);
    launch_gemm<1, true>(ah, al, wouth, woutl, bout, nullptr, out,
                         nullptr, nullptr, MM, VV, DD);
}

// round 10
// speedup vs baseline: 1.8456x; 1.8456x over previous
#include <cuda_runtime.h>
#include <cuda_bf16.h>
#include <math.h>
#include <stdint.h>

// Problem constants
#define BB   2
#define TT   2048
#define DD   1024
#define LL   4
#define HH   16
#define HD   64
#define VV   32000
#define DFF  4096
#define MM   (BB*TT)        // 4096 rows
#define QKVD 3072

// ---------------------------------------------------------------------------
// Scratch (device globals; allocation is forbidden)
// ---------------------------------------------------------------------------
__device__ float g_x  [MM*DD];
__device__ float g_qkv[MM*QKVD];

// bf16 split activations
__device__ __nv_bfloat16 g_ah[MM*DD],  g_al[MM*DD];    // LN out / attn out
__device__ __nv_bfloat16 g_fh[MM*DFF], g_fl[MM*DFF];   // FFN hidden

// bf16 split transposed weights (B side, [N,K] K-major)
__device__ __nv_bfloat16 g_wqkvh[LL*QKVD*DD], g_wqkvl[LL*QKVD*DD];
__device__ __nv_bfloat16 g_woh  [LL*DD*DD],   g_wol  [LL*DD*DD];
__device__ __nv_bfloat16 g_w1h  [LL*DFF*DD],  g_w1l  [LL*DFF*DD];
__device__ __nv_bfloat16 g_w2h  [LL*DD*DFF],  g_w2l  [LL*DD*DFF];
__device__ __nv_bfloat16 g_wouth[VV*DD],      g_woutl[VV*DD];

// ---------------------------------------------------------------------------
// PTX helpers (sm_80-compatible only)
// ---------------------------------------------------------------------------
__device__ __forceinline__ uint32_t smem_u32(const void* p) {
    return (uint32_t)__cvta_generic_to_shared(p);
}
#define CP_ASYNC16(dst, src) \
    asm volatile("cp.async.cg.shared.global [%0], [%1], 16;" :: "r"(dst), "l"(src))
#define CP_COMMIT() asm volatile("cp.async.commit_group;" ::: "memory")
#define CP_WAIT0()  asm volatile("cp.async.wait_group 0;" ::: "memory")
#define CP_WAIT1()  asm volatile("cp.async.wait_group 1;" ::: "memory")

__device__ __forceinline__ void ldmat_x4(uint32_t* r, uint32_t addr) {
    asm volatile("ldmatrix.sync.aligned.m8n8.x4.shared.b16 {%0,%1,%2,%3}, [%4];"
                 : "=r"(r[0]), "=r"(r[1]), "=r"(r[2]), "=r"(r[3]) : "r"(addr));
}
__device__ __forceinline__ void mma16816(float* d, const uint32_t* a,
                                         const uint32_t* b) {
    asm volatile(
        "mma.sync.aligned.m16n8k16.row.col.f32.bf16.bf16.f32 "
        "{%0,%1,%2,%3}, {%4,%5,%6,%7}, {%8,%9}, {%0,%1,%2,%3};"
        : "+f"(d[0]), "+f"(d[1]), "+f"(d[2]), "+f"(d[3])
        : "r"(a[0]), "r"(a[1]), "r"(a[2]), "r"(a[3]), "r"(b[0]), "r"(b[1]));
}

// ---------------------------------------------------------------------------
// Tensor GEMM: C[M,N] = (Ah+Al)[M,K] @ (Bh+Bl)[N,K]^T  (3xBF16 split)
// CTA tile 128x128, BK=32, 256 threads (2x4 warps, 64x32 warp tile),
// 2-stage cp.async pipeline, R3-style 3-pass mainloop (non-hoisted).
// 80KB smem/CTA -> 2 CTAs/SM (independent barriers overlap each other's
// sync/wait bubbles; cure for tensor=43%/issue=28%/nothing-saturated).
// MODE: bit0 +bias[n], bit1 +res[m,n], bit2 relu, bit3 write bf16 hi/lo split
// SWAPG: bm = blockIdx.x (M-fast rasterization; for huge-N logits GEMM)
// ---------------------------------------------------------------------------
#define TM 128
#define TN 128
#define BK 32
#define NTHR 256
#define SA 40                       // padded row stride (elements)
#define A_ELE (TM*SA)
#define B_ELE (TN*SA)
#define A_BYT (A_ELE*2)             // 10240
#define B_BYT (B_ELE*2)             // 10240
#define STAGE_BYT (2*A_BYT + 2*B_BYT)   // 40960
#define GEMM_SMEM (2*STAGE_BYT)         // 81920 -> 2 CTAs/SM

__device__ __forceinline__ void load_tile(uint32_t sdst, const __nv_bfloat16* g,
                                          int K, int k0, int rows4, int tid) {
    for (int i = tid; i < rows4; i += NTHR) {
        int r = i >> 2, gg = i & 3;
        CP_ASYNC16(sdst + (uint32_t)(r * 80 + gg * 16),
                   (const void*)(g + (size_t)r * K + k0 + gg * 8));
    }
}
__device__ __forceinline__ void load_chunk(uint32_t sb,
    const __nv_bfloat16* gAh, const __nv_bfloat16* gAl,
    const __nv_bfloat16* gBh, const __nv_bfloat16* gBl,
    int K, int k0, int tid) {
    load_tile(sb,                   gAh, K, k0, TM*4, tid);
    load_tile(sb + A_BYT,           gAl, K, k0, TM*4, tid);
    load_tile(sb + 2*A_BYT,         gBh, K, k0, TN*4, tid);
    load_tile(sb + 2*A_BYT + B_BYT, gBl, K, k0, TN*4, tid);
}

template<int MODE, bool SWAPG>
__global__ void __launch_bounds__(NTHR, 2) tc_gemm(
    int M, int N, int K,
    const __nv_bfloat16* __restrict__ Ah, const __nv_bfloat16* __restrict__ Al,
    const __nv_bfloat16* __restrict__ Bh, const __nv_bfloat16* __restrict__ Bl,
    const float* __restrict__ bias, const float* __restrict__ res,
    float* __restrict__ C, __nv_bfloat16* __restrict__ Ch,
    __nv_bfloat16* __restrict__ Cl)
{
    extern __shared__ __nv_bfloat16 sm[];
    uint32_t sbase = smem_u32(sm);
    int tid = threadIdx.x;
    int bm = SWAPG ? blockIdx.x : blockIdx.y;
    int bn = SWAPG ? blockIdx.y : blockIdx.x;
    int warp = tid >> 5, lane = tid & 31;
    int wm = warp & 1, wn = warp >> 1;          // warp grid 2 x 4, tile 64x32

    const __nv_bfloat16* gAh = Ah + (size_t)bm * TM * K;
    const __nv_bfloat16* gAl = Al + (size_t)bm * TM * K;
    const __nv_bfloat16* gBh = Bh + (size_t)bn * TN * K;
    const __nv_bfloat16* gBl = Bl + (size_t)bn * TN * K;

    float acc[4][4][4];
    #pragma unroll
    for (int i = 0; i < 4; i++)
        #pragma unroll
        for (int j = 0; j < 4; j++)
            #pragma unroll
            for (int u = 0; u < 4; u++) acc[i][j][u] = 0.f;

    // ldmatrix lane geometry (shared by A and B)
    int mat = lane >> 3;
    int row_off = (mat & 1) * 8 + (lane & 7);
    int kblk_off = (mat >> 1) * 8;

    const int NC = K / BK;

    // prologue: chunk 0 -> stage 0
    load_chunk(sbase, gAh, gAl, gBh, gBl, K, 0, tid);
    CP_COMMIT();

    for (int c = 0; c < NC; c++) {
        int s = c & 1;
        if (c + 1 < NC) {
            load_chunk(sbase + (uint32_t)((s ^ 1) * STAGE_BYT),
                       gAh, gAl, gBh, gBl, K, (c + 1) * BK, tid);
            CP_COMMIT();
            CP_WAIT1();
        } else {
            CP_WAIT0();
        }
        __syncthreads();

        uint32_t stg = sbase + (uint32_t)(s * STAGE_BYT);
        #pragma unroll
        for (int pass = 0; pass < 3; pass++) {
            uint32_t As = (pass == 2) ? (stg + A_BYT) : stg;
            uint32_t Bs = (pass == 1) ? (stg + 2*A_BYT + B_BYT) : (stg + 2*A_BYT);
            #pragma unroll
            for (int ks = 0; ks < 2; ks++) {
                int k0 = ks * 16 + kblk_off;
                uint32_t af[4][4], bf[2][4];
                #pragma unroll
                for (int mt = 0; mt < 4; mt++) {
                    int r = wm * 64 + mt * 16 + row_off;
                    ldmat_x4(af[mt], As + (uint32_t)((r * SA + k0) * 2));
                }
                #pragma unroll
                for (int ng = 0; ng < 2; ng++) {
                    int r = wn * 32 + ng * 16 + row_off;
                    ldmat_x4(bf[ng], Bs + (uint32_t)((r * SA + k0) * 2));
                }
                #pragma unroll
                for (int mt = 0; mt < 4; mt++)
                    #pragma unroll
                    for (int nt = 0; nt < 4; nt++) {
                        uint32_t bb[2] = { bf[nt >> 1][nt & 1],
                                           bf[nt >> 1][2 + (nt & 1)] };
                        mma16816(acc[mt][nt], af[mt], bb);
                    }
            }
        }
        __syncthreads();
    }

    // epilogue (compile-time MODE)
    int qr = lane >> 2, qc = (lane & 3) * 2;
    #pragma unroll
    for (int mt = 0; mt < 4; mt++) {
        #pragma unroll
        for (int half = 0; half < 2; half++) {
            int grow = bm * TM + wm * 64 + mt * 16 + half * 8 + qr;
            size_t rowo = (size_t)grow * N;
            #pragma unroll
            for (int nt = 0; nt < 4; nt++) {
                int gcol = bn * TN + wn * 32 + nt * 8 + qc;
                float v0 = acc[mt][nt][half * 2 + 0];
                float v1 = acc[mt][nt][half * 2 + 1];
                if (MODE & 1) { v0 += bias[gcol]; v1 += bias[gcol + 1]; }
                if (MODE & 2) {
                    const float2 r2 = *(const float2*)(res + rowo + gcol);
                    v0 += r2.x; v1 += r2.y;
                }
                if (MODE & 4) { v0 = fmaxf(v0, 0.f); v1 = fmaxf(v1, 0.f); }
                if (MODE & 8) {
                    __nv_bfloat16 h0 = __float2bfloat16(v0);
                    __nv_bfloat16 h1 = __float2bfloat16(v1);
                    __nv_bfloat162 hp; hp.x = h0; hp.y = h1;
                    __nv_bfloat162 lp;
                    lp.x = __float2bfloat16(v0 - __bfloat162float(h0));
                    lp.y = __float2bfloat16(v1 - __bfloat162float(h1));
                    *(__nv_bfloat162*)(Ch + rowo + gcol) = hp;
                    *(__nv_bfloat162*)(Cl + rowo + gcol) = lp;
                } else {
                    float2 o2; o2.x = v0; o2.y = v1;
                    *(float2*)(C + rowo + gcol) = o2;
                }
            }
        }
    }
}

// ---------------------------------------------------------------------------
// Weight transpose + split: W[K,N] fp32 -> Bt{h,l}[N,K] bf16 (4 k-tiles/block)
// ---------------------------------------------------------------------------
__device__ __forceinline__ void tsplit_body(
    const float* __restrict__ W, __nv_bfloat16* __restrict__ Bh,
    __nv_bfloat16* __restrict__ Bl, int K, int N, float (*t)[33])
{
    int n0 = blockIdx.x * 32;
    int tx = threadIdx.x & 31, ty = threadIdx.x >> 5;
    #pragma unroll
    for (int kt = 0; kt < 4; kt++) {
        int k0 = (blockIdx.y * 4 + kt) * 32;
        #pragma unroll
        for (int i = 0; i < 32; i += 8)
            t[ty + i][tx] = W[(size_t)(k0 + ty + i) * N + n0 + tx];
        __syncthreads();
        #pragma unroll
        for (int i = 0; i < 32; i += 8) {
            float v = t[tx][ty + i];
            __nv_bfloat16 hi = __float2bfloat16(v);
            size_t o = (size_t)(n0 + ty + i) * K + k0 + tx;
            Bh[o] = hi;
            Bl[o] = __float2bfloat16(v - __bfloat162float(hi));
        }
        __syncthreads();
    }
}

__global__ __launch_bounds__(256) void transpose_split_kernel(
    const float* __restrict__ W, __nv_bfloat16* __restrict__ Bh,
    __nv_bfloat16* __restrict__ Bl, int K, int N)
{
    __shared__ float t[32][33];
    tsplit_body(W, Bh, Bl, K, N, t);
}

// Fused QKV weight prep: blockIdx.z picks Wq/Wk/Wv (one launch per layer)
__global__ __launch_bounds__(256) void transpose_split_qkv_kernel(
    const float* __restrict__ Wq, const float* __restrict__ Wk,
    const float* __restrict__ Wv, __nv_bfloat16* __restrict__ Bh,
    __nv_bfloat16* __restrict__ Bl)
{
    __shared__ float t[32][33];
    int z = blockIdx.z;
    const float* W = (z == 0) ? Wq : (z == 1) ? Wk : Wv;
    size_t off = (size_t)z * DD * DD;
    tsplit_body(W, Bh + off, Bl + off, DD, DD, t);
}

// ---------------------------------------------------------------------------
// Embedding
// ---------------------------------------------------------------------------
__global__ __launch_bounds__(256) void embed_kernel(
    const int* __restrict__ ctx, const float* __restrict__ tok,
    const float* __restrict__ pos, float* __restrict__ x)
{
    int idx = blockIdx.x * 256 + threadIdx.x;
    int d  = idx & (DD - 1);
    int bt = idx >> 10;
    int t  = bt & (TT - 1);
    int v  = ctx[bt];
    x[idx] = tok[(size_t)v * DD + d] + pos[(size_t)t * DD + d];
}

// ---------------------------------------------------------------------------
// LayerNorm fused with bf16 hi/lo split output
// ---------------------------------------------------------------------------
__global__ __launch_bounds__(256) void ln_split_kernel(
    const float* __restrict__ x, const float* __restrict__ s,
    const float* __restrict__ b, __nv_bfloat16* __restrict__ yh,
    __nv_bfloat16* __restrict__ yl)
{
    int row = blockIdx.x;
    const float* xr = x + (size_t)row * DD;
    int tid = threadIdx.x;

    float v0 = xr[tid], v1 = xr[tid+256], v2 = xr[tid+512], v3 = xr[tid+768];
    float sum = v0+v1+v2+v3;
    float sq  = v0*v0+v1*v1+v2*v2+v3*v3;
    #pragma unroll
    for (int o = 16; o > 0; o >>= 1) {
        sum += __shfl_xor_sync(0xFFFFFFFFu, sum, o);
        sq  += __shfl_xor_sync(0xFFFFFFFFu, sq,  o);
    }
    __shared__ float ssum[8], ssq[8], red[2];
    if ((tid & 31) == 0) { ssum[tid>>5] = sum; ssq[tid>>5] = sq; }
    __syncthreads();
    if (tid < 32) {
        float a = (tid < 8) ? ssum[tid] : 0.f;
        float c = (tid < 8) ? ssq[tid]  : 0.f;
        #pragma unroll
        for (int o = 4; o > 0; o >>= 1) {
            a += __shfl_xor_sync(0xFFFFFFFFu, a, o);
            c += __shfl_xor_sync(0xFFFFFFFFu, c, o);
        }
        if (tid == 0) { red[0] = a; red[1] = c; }
    }
    __syncthreads();
    float mean = red[0] * (1.f/DD);
    float var  = red[1] * (1.f/DD) - mean*mean;
    float inv  = rsqrtf(var + 1e-5f);
    #pragma unroll
    for (int i = 0; i < 4; i++) {
        int c = tid + i*256;
        float val = (xr[c] - mean) * inv * s[c] + b[c];
        __nv_bfloat16 hi = __float2bfloat16(val);
        size_t o = (size_t)row * DD + c;
        yh[o] = hi;
        yl[o] = __float2bfloat16(val - __bfloat162float(hi));
    }
}

// ---------------------------------------------------------------------------
// Flash attention (causal), QKV packed [M,3072]; writes bf16 hi/lo [M,1024]
// (fp32 scalar math — the R7/R8-measured version; f32x2 experiment reverted)
// ---------------------------------------------------------------------------
__global__ __launch_bounds__(128) void attn_kernel(
    const float* __restrict__ QKV, __nv_bfloat16* __restrict__ Oh,
    __nv_bfloat16* __restrict__ Ol)
{
    int qt = blockIdx.x, h = blockIdx.y, b = blockIdx.z;
    int tid = threadIdx.x;
    int q_idx = qt * 128 + tid;

    const float* qp = QKV + ((size_t)(b*TT) + q_idx) * QKVD + h * HD;

    float qr[64];
    #pragma unroll
    for (int c = 0; c < 16; c++) {
        float4 t4 = *(const float4*)(qp + c*4);
        qr[4*c+0] = t4.x * 0.125f; qr[4*c+1] = t4.y * 0.125f;
        qr[4*c+2] = t4.z * 0.125f; qr[4*c+3] = t4.w * 0.125f;
    }
    float ob[64];
    #pragma unroll
    for (int d = 0; d < 64; d++) ob[d] = 0.f;
    float m = -1e30f, lsum = 0.f;

    __shared__ float4 Ks[16][16];
    __shared__ float4 Vs[16][16];

    int kend = qt * 128 + 128;
    for (int k0 = 0; k0 < kend; k0 += 16) {
        __syncthreads();
        #pragma unroll
        for (int i = 0; i < 2; i++) {
            int idx = tid + i*128;
            int r = idx >> 4, c = idx & 15;
            size_t rb = ((size_t)(b*TT) + k0 + r) * QKVD + h * HD + c*4;
            Ks[r][c] = *(const float4*)(QKV + rb + DD);
            Vs[r][c] = *(const float4*)(QKV + rb + 2*DD);
        }
        __syncthreads();

        float s[16];
        #pragma unroll
        for (int j = 0; j < 16; j++) {
            float acc = 0.f;
            #pragma unroll
            for (int c = 0; c < 16; c++) {
                float4 kk = Ks[j][c];
                acc += qr[4*c+0]*kk.x + qr[4*c+1]*kk.y
                     + qr[4*c+2]*kk.z + qr[4*c+3]*kk.w;
            }
            s[j] = (k0 + j <= q_idx) ? acc : -1e30f;
        }
        float mt = m;
        #pragma unroll
        for (int j = 0; j < 16; j++) mt = fmaxf(mt, s[j]);
        float corr = __expf(m - mt);
        m = mt;
        lsum *= corr;
        #pragma unroll
        for (int d = 0; d < 64; d++) ob[d] *= corr;

        #pragma unroll
        for (int j = 0; j < 16; j++) {
            float p = __expf(s[j] - m);
            lsum += p;
            #pragma unroll
            for (int c = 0; c < 16; c++) {
                float4 vv = Vs[j][c];
                ob[4*c+0] += p * vv.x; ob[4*c+1] += p * vv.y;
                ob[4*c+2] += p * vv.z; ob[4*c+3] += p * vv.w;
            }
        }
    }

    float inv = 1.f / lsum;
    size_t ob_off = ((size_t)(b*TT) + q_idx) * DD + h * HD;
    #pragma unroll
    for (int c = 0; c < 32; c++) {
        float u0 = ob[2*c+0]*inv, u1 = ob[2*c+1]*inv;
        __nv_bfloat16 h0 = __float2bfloat16(u0);
        __nv_bfloat16 h1 = __float2bfloat16(u1);
        __nv_bfloat162 hp; hp.x = h0; hp.y = h1;
        __nv_bfloat162 lp;
        lp.x = __float2bfloat16(u0 - __bfloat162float(h0));
        lp.y = __float2bfloat16(u1 - __bfloat162float(h1));
        *(__nv_bfloat162*)(Oh + ob_off + 2*c) = hp;
        *(__nv_bfloat162*)(Ol + ob_off + 2*c) = lp;
    }
}

// ---------------------------------------------------------------------------
// Host orchestration
// ---------------------------------------------------------------------------
template<int MODE, bool SWAPG>
static void launch_gemm(const __nv_bfloat16* Ah, const __nv_bfloat16* Al,
                        const __nv_bfloat16* Bh, const __nv_bfloat16* Bl,
                        const float* bias, const float* res, float* C,
                        __nv_bfloat16* Ch, __nv_bfloat16* Cl,
                        int M, int N, int K)
{
    dim3 grid = SWAPG ? dim3(M / TM, N / TN) : dim3(N / TN, M / TM);
    tc_gemm<MODE, SWAPG><<<grid, NTHR, GEMM_SMEM>>>(M, N, K, Ah, Al, Bh, Bl,
                                                    bias, res, C, Ch, Cl);
}

static void launch_tsplit(const float* W, __nv_bfloat16* Bh, __nv_bfloat16* Bl,
                          int K, int N)
{
    dim3 grid(N / 32, K / 128);
    transpose_split_kernel<<<grid, 256>>>(W, Bh, Bl, K, N);
}

extern "C" void kernel_launch(void* const* d_in, const int* in_sizes, int n_in,
                              void* d_out, int out_size)
{
    const int*   ctx  = (const int*)  d_in[0];
    const float* tok  = (const float*)d_in[1];
    const float* pos  = (const float*)d_in[2];
    const float* Wq   = (const float*)d_in[3];
    const float* Wk   = (const float*)d_in[4];
    const float* Wv   = (const float*)d_in[5];
    const float* Wo   = (const float*)d_in[6];
    const float* bo   = (const float*)d_in[7];
    const float* ln1s = (const float*)d_in[8];
    const float* ln1b = (const float*)d_in[9];
    const float* W1   = (const float*)d_in[10];
    const float* b1   = (const float*)d_in[11];
    const float* W2   = (const float*)d_in[12];
    const float* b2   = (const float*)d_in[13];
    const float* ln2s = (const float*)d_in[14];
    const float* ln2b = (const float*)d_in[15];
    const float* lnfs = (const float*)d_in[16];
    const float* lnfb = (const float*)d_in[17];
    const float* Wout = (const float*)d_in[18];
    const float* bout = (const float*)d_in[19];
    float* out = (float*)d_out;

    // smem opt-in for all tc_gemm instantiations (unconditional; no static state)
    cudaFuncSetAttribute(tc_gemm<0,false>,  cudaFuncAttributeMaxDynamicSharedMemorySize, GEMM_SMEM);
    cudaFuncSetAttribute(tc_gemm<3,false>,  cudaFuncAttributeMaxDynamicSharedMemorySize, GEMM_SMEM);
    cudaFuncSetAttribute(tc_gemm<13,false>, cudaFuncAttributeMaxDynamicSharedMemorySize, GEMM_SMEM);
    cudaFuncSetAttribute(tc_gemm<1,true>,   cudaFuncAttributeMaxDynamicSharedMemorySize, GEMM_SMEM);

    float *x, *qkv;
    __nv_bfloat16 *ah, *al, *fh, *fl;
    __nv_bfloat16 *wqkvh, *wqkvl, *woh, *wol, *w1h, *w1l, *w2h, *w2l, *wouth, *woutl;
    cudaGetSymbolAddress((void**)&x,    g_x);
    cudaGetSymbolAddress((void**)&qkv,  g_qkv);
    cudaGetSymbolAddress((void**)&ah,   g_ah);
    cudaGetSymbolAddress((void**)&al,   g_al);
    cudaGetSymbolAddress((void**)&fh,   g_fh);
    cudaGetSymbolAddress((void**)&fl,   g_fl);
    cudaGetSymbolAddress((void**)&wqkvh,g_wqkvh);
    cudaGetSymbolAddress((void**)&wqkvl,g_wqkvl);
    cudaGetSymbolAddress((void**)&woh,  g_woh);
    cudaGetSymbolAddress((void**)&wol,  g_wol);
    cudaGetSymbolAddress((void**)&w1h,  g_w1h);
    cudaGetSymbolAddress((void**)&w1l,  g_w1l);
    cudaGetSymbolAddress((void**)&w2h,  g_w2h);
    cudaGetSymbolAddress((void**)&w2l,  g_w2l);
    cudaGetSymbolAddress((void**)&wouth,g_wouth);
    cudaGetSymbolAddress((void**)&woutl,g_woutl);

    // Stream index 0: fused layer-0 QKV weight prep (one launch)
    {
        dim3 grid(DD / 32, DD / 128, 3);
        transpose_split_qkv_kernel<<<grid, 256>>>(Wq, Wk, Wv, wqkvh, wqkvl);
    }
    // Index 1: embedding
    embed_kernel<<<(MM*DD)/256, 256>>>(ctx, tok, pos, x);
    // Index 2: LN1 (layer 0)
    ln_split_kernel<<<MM, 256>>>(x, ln1s, ln1b, ah, al);
    // Index 3: layer-0 QKV GEMM  (harness offset +2 -> ncu global index 5)
    launch_gemm<0, false>(ah, al, wqkvh, wqkvl, nullptr, nullptr, qkv,
                          nullptr, nullptr, MM, QKVD, DD);

    // Remaining weight prep
    for (int l = 0; l < LL; l++) {
        size_t qo = (size_t)l * QKVD * DD;
        if (l > 0) {
            dim3 grid(DD / 32, DD / 128, 3);
            transpose_split_qkv_kernel<<<grid, 256>>>(
                Wq + (size_t)l*DD*DD, Wk + (size_t)l*DD*DD, Wv + (size_t)l*DD*DD,
                wqkvh + qo, wqkvl + qo);
        }
        launch_tsplit(Wo + (size_t)l*DD*DD,  woh + (size_t)l*DD*DD,  wol + (size_t)l*DD*DD,  DD, DD);
        launch_tsplit(W1 + (size_t)l*DD*DFF, w1h + (size_t)l*DFF*DD, w1l + (size_t)l*DFF*DD, DD, DFF);
        launch_tsplit(W2 + (size_t)l*DFF*DD, w2h + (size_t)l*DD*DFF, w2l + (size_t)l*DD*DFF, DFF, DD);
    }
    launch_tsplit(Wout, wouth, woutl, DD, VV);

    for (int l = 0; l < LL; l++) {
        const __nv_bfloat16* lwqh = wqkvh + (size_t)l*QKVD*DD;
        const __nv_bfloat16* lwql = wqkvl + (size_t)l*QKVD*DD;
        const __nv_bfloat16* lwoh = woh + (size_t)l*DD*DD;
        const __nv_bfloat16* lwol = wol + (size_t)l*DD*DD;
        const __nv_bfloat16* lw1h = w1h + (size_t)l*DFF*DD;
        const __nv_bfloat16* lw1l = w1l + (size_t)l*DFF*DD;
        const __nv_bfloat16* lw2h = w2h + (size_t)l*DD*DFF;
        const __nv_bfloat16* lw2l = w2l + (size_t)l*DD*DFF;

        if (l > 0) {
            ln_split_kernel<<<MM, 256>>>(x, ln1s + l*DD, ln1b + l*DD, ah, al);
            launch_gemm<0, false>(ah, al, lwqh, lwql, nullptr, nullptr, qkv,
                                  nullptr, nullptr, MM, QKVD, DD);
        }

        // attention -> ah/al (bf16 split)
        {
            dim3 grid(TT/128, HH, BB);
            attn_kernel<<<grid, 128>>>(qkv, ah, al);
        }

        // x = x + att @ Wo + bo
        launch_gemm<3, false>(ah, al, lwoh, lwol, bo + l*DD, x, x,
                              nullptr, nullptr, MM, DD, DD);

        // ah/al = split(LN2(x)); fh/fl = split(relu(ah @ W1 + b1))
        ln_split_kernel<<<MM, 256>>>(x, ln2s + l*DD, ln2b + l*DD, ah, al);
        launch_gemm<13, false>(ah, al, lw1h, lw1l, b1 + l*DFF, nullptr, nullptr,
                               fh, fl, MM, DFF, DD);

        // x = x + fh @ W2 + b2
        launch_gemm<3, false>(fh, fl, lw2h, lw2l, b2 + l*DD, x, x,
                              nullptr, nullptr, MM, DD, DFF);
    }

    // final LN + logits (M-fast rasterization: stream 131MB B once)
    ln_split_kernel<<<MM, 256>>>(x, lnfs, lnfb, ah, al);
    launch_gemm<1, true>(ah, al, wouth, woutl, bout, nullptr, out,
                         nullptr, nullptr, MM, VV, DD);
}

// round 11
// speedup vs baseline: 1.8494x; 1.0020x over previous
#include <cuda_runtime.h>
#include <cuda_bf16.h>
#include <math.h>
#include <stdint.h>

// Problem constants
#define BB   2
#define TT   2048
#define DD   1024
#define LL   4
#define HH   16
#define HD   64
#define VV   32000
#define DFF  4096
#define MM   (BB*TT)        // 4096 rows
#define QKVD 3072

// ---------------------------------------------------------------------------
// Scratch (device globals; allocation is forbidden)
// ---------------------------------------------------------------------------
__device__ float g_x  [MM*DD];
__device__ float g_qkv[MM*QKVD];

// bf16 split activations
__device__ __nv_bfloat16 g_ah[MM*DD],  g_al[MM*DD];    // LN out / attn out
__device__ __nv_bfloat16 g_fh[MM*DFF], g_fl[MM*DFF];   // FFN hidden

// bf16 split transposed weights (B side, [N,K] K-major)
__device__ __nv_bfloat16 g_wqkvh[LL*QKVD*DD], g_wqkvl[LL*QKVD*DD];
__device__ __nv_bfloat16 g_woh  [LL*DD*DD],   g_wol  [LL*DD*DD];
__device__ __nv_bfloat16 g_w1h  [LL*DFF*DD],  g_w1l  [LL*DFF*DD];
__device__ __nv_bfloat16 g_w2h  [LL*DD*DFF],  g_w2l  [LL*DD*DFF];
__device__ __nv_bfloat16 g_wouth[VV*DD],      g_woutl[VV*DD];

// ---------------------------------------------------------------------------
// PTX helpers (sm_80-compatible only)
// ---------------------------------------------------------------------------
__device__ __forceinline__ uint32_t smem_u32(const void* p) {
    return (uint32_t)__cvta_generic_to_shared(p);
}
#define CP_ASYNC16(dst, src) \
    asm volatile("cp.async.cg.shared.global [%0], [%1], 16;" :: "r"(dst), "l"(src))
#define CP_COMMIT() asm volatile("cp.async.commit_group;" ::: "memory")
#define CP_WAIT0()  asm volatile("cp.async.wait_group 0;" ::: "memory")
#define CP_WAIT1()  asm volatile("cp.async.wait_group 1;" ::: "memory")

__device__ __forceinline__ void ldmat_x4(uint32_t* r, uint32_t addr) {
    asm volatile("ldmatrix.sync.aligned.m8n8.x4.shared.b16 {%0,%1,%2,%3}, [%4];"
                 : "=r"(r[0]), "=r"(r[1]), "=r"(r[2]), "=r"(r[3]) : "r"(addr));
}
__device__ __forceinline__ void mma16816(float* d, const uint32_t* a,
                                         const uint32_t* b) {
    asm volatile(
        "mma.sync.aligned.m16n8k16.row.col.f32.bf16.bf16.f32 "
        "{%0,%1,%2,%3}, {%4,%5,%6,%7}, {%8,%9}, {%0,%1,%2,%3};"
        : "+f"(d[0]), "+f"(d[1]), "+f"(d[2]), "+f"(d[3])
        : "r"(a[0]), "r"(a[1]), "r"(a[2]), "r"(a[3]), "r"(b[0]), "r"(b[1]));
}

// ---------------------------------------------------------------------------
// Tensor GEMM: C[M,N] = (Ah+Al)[M,K] @ (Bh+Bl)[N,K]^T  (3xBF16 split)
// CTA tile 128x128, BK=32, 256 threads (2x4 warps, 64x32 warp tile),
// 2-stage cp.async pipeline, 2 CTAs/SM (80KB smem, 128 regs).
// Mainloop: R10 skeleton with the redundant Ah reload removed
// (14 ldmat.x4 per ks-group instead of 18; max fragment liveness 24 regs).
// MODE: bit0 +bias[n], bit1 +res[m,n], bit2 relu, bit3 write bf16 hi/lo split
// SWAPG: bm = blockIdx.x (M-fast rasterization; for huge-N logits GEMM)
// ---------------------------------------------------------------------------
#define TM 128
#define TN 128
#define BK 32
#define NTHR 256
#define SA 40                       // padded row stride (elements)
#define A_ELE (TM*SA)
#define B_ELE (TN*SA)
#define A_BYT (A_ELE*2)             // 10240
#define B_BYT (B_ELE*2)             // 10240
#define STAGE_BYT (2*A_BYT + 2*B_BYT)   // 40960
#define GEMM_SMEM (2*STAGE_BYT)         // 81920 -> 2 CTAs/SM

__device__ __forceinline__ void load_tile(uint32_t sdst, const __nv_bfloat16* g,
                                          int K, int k0, int rows4, int tid) {
    for (int i = tid; i < rows4; i += NTHR) {
        int r = i >> 2, gg = i & 3;
        CP_ASYNC16(sdst + (uint32_t)(r * 80 + gg * 16),
                   (const void*)(g + (size_t)r * K + k0 + gg * 8));
    }
}
__device__ __forceinline__ void load_chunk(uint32_t sb,
    const __nv_bfloat16* gAh, const __nv_bfloat16* gAl,
    const __nv_bfloat16* gBh, const __nv_bfloat16* gBl,
    int K, int k0, int tid) {
    load_tile(sb,                   gAh, K, k0, TM*4, tid);
    load_tile(sb + A_BYT,           gAl, K, k0, TM*4, tid);
    load_tile(sb + 2*A_BYT,         gBh, K, k0, TN*4, tid);
    load_tile(sb + 2*A_BYT + B_BYT, gBl, K, k0, TN*4, tid);
}

template<int MODE, bool SWAPG>
__global__ void __launch_bounds__(NTHR, 2) tc_gemm(
    int M, int N, int K,
    const __nv_bfloat16* __restrict__ Ah, const __nv_bfloat16* __restrict__ Al,
    const __nv_bfloat16* __restrict__ Bh, const __nv_bfloat16* __restrict__ Bl,
    const float* __restrict__ bias, const float* __restrict__ res,
    float* __restrict__ C, __nv_bfloat16* __restrict__ Ch,
    __nv_bfloat16* __restrict__ Cl)
{
    extern __shared__ __nv_bfloat16 sm[];
    uint32_t sbase = smem_u32(sm);
    int tid = threadIdx.x;
    int bm = SWAPG ? blockIdx.x : blockIdx.y;
    int bn = SWAPG ? blockIdx.y : blockIdx.x;
    int warp = tid >> 5, lane = tid & 31;
    int wm = warp & 1, wn = warp >> 1;          // warp grid 2 x 4, tile 64x32

    const __nv_bfloat16* gAh = Ah + (size_t)bm * TM * K;
    const __nv_bfloat16* gAl = Al + (size_t)bm * TM * K;
    const __nv_bfloat16* gBh = Bh + (size_t)bn * TN * K;
    const __nv_bfloat16* gBl = Bl + (size_t)bn * TN * K;

    float acc[4][4][4];
    #pragma unroll
    for (int i = 0; i < 4; i++)
        #pragma unroll
        for (int j = 0; j < 4; j++)
            #pragma unroll
            for (int u = 0; u < 4; u++) acc[i][j][u] = 0.f;

    // ldmatrix lane geometry (shared by A and B)
    int mat = lane >> 3;
    int row_off = (mat & 1) * 8 + (lane & 7);
    int kblk_off = (mat >> 1) * 8;

    const int NC = K / BK;

    // prologue: chunk 0 -> stage 0
    load_chunk(sbase, gAh, gAl, gBh, gBl, K, 0, tid);
    CP_COMMIT();

    for (int c = 0; c < NC; c++) {
        int s = c & 1;
        if (c + 1 < NC) {
            load_chunk(sbase + (uint32_t)((s ^ 1) * STAGE_BYT),
                       gAh, gAl, gBh, gBl, K, (c + 1) * BK, tid);
            CP_COMMIT();
            CP_WAIT1();
        } else {
            CP_WAIT0();
        }
        __syncthreads();

        uint32_t stg = sbase + (uint32_t)(s * STAGE_BYT);
        uint32_t Ash = stg, Asl = stg + A_BYT;
        uint32_t Bsh = stg + 2*A_BYT, Bsl = stg + 2*A_BYT + B_BYT;

        #pragma unroll
        for (int ks = 0; ks < 2; ks++) {
            int k0 = ks * 16 + kblk_off;
            uint32_t af[4][4], bf[2][4];
            // pass 0: Ah * Bh
            #pragma unroll
            for (int mt = 0; mt < 4; mt++) {
                int r = wm * 64 + mt * 16 + row_off;
                ldmat_x4(af[mt], Ash + (uint32_t)((r * SA + k0) * 2));
            }
            #pragma unroll
            for (int ng = 0; ng < 2; ng++) {
                int r = wn * 32 + ng * 16 + row_off;
                ldmat_x4(bf[ng], Bsh + (uint32_t)((r * SA + k0) * 2));
            }
            #pragma unroll
            for (int mt = 0; mt < 4; mt++)
                #pragma unroll
                for (int nt = 0; nt < 4; nt++) {
                    uint32_t bb[2] = { bf[nt >> 1][nt & 1],
                                       bf[nt >> 1][2 + (nt & 1)] };
                    mma16816(acc[mt][nt], af[mt], bb);
                }
            // pass 1: Ah * Bl  (af stays live; only B reloaded)
            #pragma unroll
            for (int ng = 0; ng < 2; ng++) {
                int r = wn * 32 + ng * 16 + row_off;
                ldmat_x4(bf[ng], Bsl + (uint32_t)((r * SA + k0) * 2));
            }
            #pragma unroll
            for (int mt = 0; mt < 4; mt++)
                #pragma unroll
                for (int nt = 0; nt < 4; nt++) {
                    uint32_t bb[2] = { bf[nt >> 1][nt & 1],
                                       bf[nt >> 1][2 + (nt & 1)] };
                    mma16816(acc[mt][nt], af[mt], bb);
                }
            // pass 2: Al * Bh  (reload both; liveness never exceeds 24 regs)
            #pragma unroll
            for (int mt = 0; mt < 4; mt++) {
                int r = wm * 64 + mt * 16 + row_off;
                ldmat_x4(af[mt], Asl + (uint32_t)((r * SA + k0) * 2));
            }
            #pragma unroll
            for (int ng = 0; ng < 2; ng++) {
                int r = wn * 32 + ng * 16 + row_off;
                ldmat_x4(bf[ng], Bsh + (uint32_t)((r * SA + k0) * 2));
            }
            #pragma unroll
            for (int mt = 0; mt < 4; mt++)
                #pragma unroll
                for (int nt = 0; nt < 4; nt++) {
                    uint32_t bb[2] = { bf[nt >> 1][nt & 1],
                                       bf[nt >> 1][2 + (nt & 1)] };
                    mma16816(acc[mt][nt], af[mt], bb);
                }
        }
        __syncthreads();
    }

    // epilogue (compile-time MODE)
    int qr = lane >> 2, qc = (lane & 3) * 2;
    #pragma unroll
    for (int mt = 0; mt < 4; mt++) {
        #pragma unroll
        for (int half = 0; half < 2; half++) {
            int grow = bm * TM + wm * 64 + mt * 16 + half * 8 + qr;
            size_t rowo = (size_t)grow * N;
            #pragma unroll
            for (int nt = 0; nt < 4; nt++) {
                int gcol = bn * TN + wn * 32 + nt * 8 + qc;
                float v0 = acc[mt][nt][half * 2 + 0];
                float v1 = acc[mt][nt][half * 2 + 1];
                if (MODE & 1) { v0 += bias[gcol]; v1 += bias[gcol + 1]; }
                if (MODE & 2) {
                    const float2 r2 = *(const float2*)(res + rowo + gcol);
                    v0 += r2.x; v1 += r2.y;
                }
                if (MODE & 4) { v0 = fmaxf(v0, 0.f); v1 = fmaxf(v1, 0.f); }
                if (MODE & 8) {
                    __nv_bfloat16 h0 = __float2bfloat16(v0);
                    __nv_bfloat16 h1 = __float2bfloat16(v1);
                    __nv_bfloat162 hp; hp.x = h0; hp.y = h1;
                    __nv_bfloat162 lp;
                    lp.x = __float2bfloat16(v0 - __bfloat162float(h0));
                    lp.y = __float2bfloat16(v1 - __bfloat162float(h1));
                    *(__nv_bfloat162*)(Ch + rowo + gcol) = hp;
                    *(__nv_bfloat162*)(Cl + rowo + gcol) = lp;
                } else {
                    float2 o2; o2.x = v0; o2.y = v1;
                    *(float2*)(C + rowo + gcol) = o2;
                }
            }
        }
    }
}

// ---------------------------------------------------------------------------
// Weight transpose + split: W[K,N] fp32 -> Bt{h,l}[N,K] bf16
// Unbatched 32x32 tiles (R3-measured: ~1.5 TB/s vs 0.7 TB/s batched)
// ---------------------------------------------------------------------------
__device__ __forceinline__ void tsplit_body(
    const float* __restrict__ W, __nv_bfloat16* __restrict__ Bh,
    __nv_bfloat16* __restrict__ Bl, int K, int N, float (*t)[33])
{
    int n0 = blockIdx.x * 32, k0 = blockIdx.y * 32;
    int tx = threadIdx.x & 31, ty = threadIdx.x >> 5;   // ty 0..7
    #pragma unroll
    for (int i = 0; i < 32; i += 8)
        t[ty + i][tx] = W[(size_t)(k0 + ty + i) * N + n0 + tx];
    __syncthreads();
    #pragma unroll
    for (int i = 0; i < 32; i += 8) {
        float v = t[tx][ty + i];
        __nv_bfloat16 hi = __float2bfloat16(v);
        size_t o = (size_t)(n0 + ty + i) * K + k0 + tx;
        Bh[o] = hi;
        Bl[o] = __float2bfloat16(v - __bfloat162float(hi));
    }
}

__global__ __launch_bounds__(256) void transpose_split_kernel(
    const float* __restrict__ W, __nv_bfloat16* __restrict__ Bh,
    __nv_bfloat16* __restrict__ Bl, int K, int N)
{
    __shared__ float t[32][33];
    tsplit_body(W, Bh, Bl, K, N, t);
}

// Fused QKV weight prep: blockIdx.z picks Wq/Wk/Wv
__global__ __launch_bounds__(256) void transpose_split_qkv_kernel(
    const float* __restrict__ Wq, const float* __restrict__ Wk,
    const float* __restrict__ Wv, __nv_bfloat16* __restrict__ Bh,
    __nv_bfloat16* __restrict__ Bl)
{
    __shared__ float t[32][33];
    int z = blockIdx.z;
    const float* W = (z == 0) ? Wq : (z == 1) ? Wk : Wv;
    size_t off = (size_t)z * DD * DD;
    tsplit_body(W, Bh + off, Bl + off, DD, DD, t);
}

// ---------------------------------------------------------------------------
// Embedding
// ---------------------------------------------------------------------------
__global__ __launch_bounds__(256) void embed_kernel(
    const int* __restrict__ ctx, const float* __restrict__ tok,
    const float* __restrict__ pos, float* __restrict__ x)
{
    int idx = blockIdx.x * 256 + threadIdx.x;
    int d  = idx & (DD - 1);
    int bt = idx >> 10;
    int t  = bt & (TT - 1);
    int v  = ctx[bt];
    x[idx] = tok[(size_t)v * DD + d] + pos[(size_t)t * DD + d];
}

// ---------------------------------------------------------------------------
// LayerNorm fused with bf16 hi/lo split output
// ---------------------------------------------------------------------------
__global__ __launch_bounds__(256) void ln_split_kernel(
    const float* __restrict__ x, const float* __restrict__ s,
    const float* __restrict__ b, __nv_bfloat16* __restrict__ yh,
    __nv_bfloat16* __restrict__ yl)
{
    int row = blockIdx.x;
    const float* xr = x + (size_t)row * DD;
    int tid = threadIdx.x;

    float v0 = xr[tid], v1 = xr[tid+256], v2 = xr[tid+512], v3 = xr[tid+768];
    float sum = v0+v1+v2+v3;
    float sq  = v0*v0+v1*v1+v2*v2+v3*v3;
    #pragma unroll
    for (int o = 16; o > 0; o >>= 1) {
        sum += __shfl_xor_sync(0xFFFFFFFFu, sum, o);
        sq  += __shfl_xor_sync(0xFFFFFFFFu, sq,  o);
    }
    __shared__ float ssum[8], ssq[8], red[2];
    if ((tid & 31) == 0) { ssum[tid>>5] = sum; ssq[tid>>5] = sq; }
    __syncthreads();
    if (tid < 32) {
        float a = (tid < 8) ? ssum[tid] : 0.f;
        float c = (tid < 8) ? ssq[tid]  : 0.f;
        #pragma unroll
        for (int o = 4; o > 0; o >>= 1) {
            a += __shfl_xor_sync(0xFFFFFFFFu, a, o);
            c += __shfl_xor_sync(0xFFFFFFFFu, c, o);
        }
        if (tid == 0) { red[0] = a; red[1] = c; }
    }
    __syncthreads();
    float mean = red[0] * (1.f/DD);
    float var  = red[1] * (1.f/DD) - mean*mean;
    float inv  = rsqrtf(var + 1e-5f);
    #pragma unroll
    for (int i = 0; i < 4; i++) {
        int c = tid + i*256;
        float val = (xr[c] - mean) * inv * s[c] + b[c];
        __nv_bfloat16 hi = __float2bfloat16(val);
        size_t o = (size_t)row * DD + c;
        yh[o] = hi;
        yl[o] = __float2bfloat16(val - __bfloat162float(hi));
    }
}

// ---------------------------------------------------------------------------
// Flash attention (causal), QKV packed [M,3072]; writes bf16 hi/lo [M,1024]
// ---------------------------------------------------------------------------
__global__ __launch_bounds__(128) void attn_kernel(
    const float* __restrict__ QKV, __nv_bfloat16* __restrict__ Oh,
    __nv_bfloat16* __restrict__ Ol)
{
    int qt = blockIdx.x, h = blockIdx.y, b = blockIdx.z;
    int tid = threadIdx.x;
    int q_idx = qt * 128 + tid;

    const float* qp = QKV + ((size_t)(b*TT) + q_idx) * QKVD + h * HD;

    float qr[64];
    #pragma unroll
    for (int c = 0; c < 16; c++) {
        float4 t4 = *(const float4*)(qp + c*4);
        qr[4*c+0] = t4.x * 0.125f; qr[4*c+1] = t4.y * 0.125f;
        qr[4*c+2] = t4.z * 0.125f; qr[4*c+3] = t4.w * 0.125f;
    }
    float ob[64];
    #pragma unroll
    for (int d = 0; d < 64; d++) ob[d] = 0.f;
    float m = -1e30f, lsum = 0.f;

    __shared__ float4 Ks[16][16];
    __shared__ float4 Vs[16][16];

    int kend = qt * 128 + 128;
    for (int k0 = 0; k0 < kend; k0 += 16) {
        __syncthreads();
        #pragma unroll
        for (int i = 0; i < 2; i++) {
            int idx = tid + i*128;
            int r = idx >> 4, c = idx & 15;
            size_t rb = ((size_t)(b*TT) + k0 + r) * QKVD + h * HD + c*4;
            Ks[r][c] = *(const float4*)(QKV + rb + DD);
            Vs[r][c] = *(const float4*)(QKV + rb + 2*DD);
        }
        __syncthreads();

        float s[16];
        #pragma unroll
        for (int j = 0; j < 16; j++) {
            float acc = 0.f;
            #pragma unroll
            for (int c = 0; c < 16; c++) {
                float4 kk = Ks[j][c];
                acc += qr[4*c+0]*kk.x + qr[4*c+1]*kk.y
                     + qr[4*c+2]*kk.z + qr[4*c+3]*kk.w;
            }
            s[j] = (k0 + j <= q_idx) ? acc : -1e30f;
        }
        float mt = m;
        #pragma unroll
        for (int j = 0; j < 16; j++) mt = fmaxf(mt, s[j]);
        float corr = __expf(m - mt);
        m = mt;
        lsum *= corr;
        #pragma unroll
        for (int d = 0; d < 64; d++) ob[d] *= corr;

        #pragma unroll
        for (int j = 0; j < 16; j++) {
            float p = __expf(s[j] - m);
            lsum += p;
            #pragma unroll
            for (int c = 0; c < 16; c++) {
                float4 vv = Vs[j][c];
                ob[4*c+0] += p * vv.x; ob[4*c+1] += p * vv.y;
                ob[4*c+2] += p * vv.z; ob[4*c+3] += p * vv.w;
            }
        }
    }

    float inv = 1.f / lsum;
    size_t ob_off = ((size_t)(b*TT) + q_idx) * DD + h * HD;
    #pragma unroll
    for (int c = 0; c < 32; c++) {
        float u0 = ob[2*c+0]*inv, u1 = ob[2*c+1]*inv;
        __nv_bfloat16 h0 = __float2bfloat16(u0);
        __nv_bfloat16 h1 = __float2bfloat16(u1);
        __nv_bfloat162 hp; hp.x = h0; hp.y = h1;
        __nv_bfloat162 lp;
        lp.x = __float2bfloat16(u0 - __bfloat162float(h0));
        lp.y = __float2bfloat16(u1 - __bfloat162float(h1));
        *(__nv_bfloat162*)(Oh + ob_off + 2*c) = hp;
        *(__nv_bfloat162*)(Ol + ob_off + 2*c) = lp;
    }
}

// ---------------------------------------------------------------------------
// Host orchestration
// ---------------------------------------------------------------------------
template<int MODE, bool SWAPG>
static void launch_gemm(const __nv_bfloat16* Ah, const __nv_bfloat16* Al,
                        const __nv_bfloat16* Bh, const __nv_bfloat16* Bl,
                        const float* bias, const float* res, float* C,
                        __nv_bfloat16* Ch, __nv_bfloat16* Cl,
                        int M, int N, int K)
{
    dim3 grid = SWAPG ? dim3(M / TM, N / TN) : dim3(N / TN, M / TM);
    tc_gemm<MODE, SWAPG><<<grid, NTHR, GEMM_SMEM>>>(M, N, K, Ah, Al, Bh, Bl,
                                                    bias, res, C, Ch, Cl);
}

static void launch_tsplit(const float* W, __nv_bfloat16* Bh, __nv_bfloat16* Bl,
                          int K, int N)
{
    dim3 grid(N / 32, K / 32);
    transpose_split_kernel<<<grid, 256>>>(W, Bh, Bl, K, N);
}

extern "C" void kernel_launch(void* const* d_in, const int* in_sizes, int n_in,
                              void* d_out, int out_size)
{
    const int*   ctx  = (const int*)  d_in[0];
    const float* tok  = (const float*)d_in[1];
    const float* pos  = (const float*)d_in[2];
    const float* Wq   = (const float*)d_in[3];
    const float* Wk   = (const float*)d_in[4];
    const float* Wv   = (const float*)d_in[5];
    const float* Wo   = (const float*)d_in[6];
    const float* bo   = (const float*)d_in[7];
    const float* ln1s = (const float*)d_in[8];
    const float* ln1b = (const float*)d_in[9];
    const float* W1   = (const float*)d_in[10];
    const float* b1   = (const float*)d_in[11];
    const float* W2   = (const float*)d_in[12];
    const float* b2   = (const float*)d_in[13];
    const float* ln2s = (const float*)d_in[14];
    const float* ln2b = (const float*)d_in[15];
    const float* lnfs = (const float*)d_in[16];
    const float* lnfb = (const float*)d_in[17];
    const float* Wout = (const float*)d_in[18];
    const float* bout = (const float*)d_in[19];
    float* out = (float*)d_out;

    // smem opt-in for all tc_gemm instantiations (unconditional; no static state)
    cudaFuncSetAttribute(tc_gemm<0,false>,  cudaFuncAttributeMaxDynamicSharedMemorySize, GEMM_SMEM);
    cudaFuncSetAttribute(tc_gemm<3,false>,  cudaFuncAttributeMaxDynamicSharedMemorySize, GEMM_SMEM);
    cudaFuncSetAttribute(tc_gemm<13,false>, cudaFuncAttributeMaxDynamicSharedMemorySize, GEMM_SMEM);
    cudaFuncSetAttribute(tc_gemm<1,true>,   cudaFuncAttributeMaxDynamicSharedMemorySize, GEMM_SMEM);

    float *x, *qkv;
    __nv_bfloat16 *ah, *al, *fh, *fl;
    __nv_bfloat16 *wqkvh, *wqkvl, *woh, *wol, *w1h, *w1l, *w2h, *w2l, *wouth, *woutl;
    cudaGetSymbolAddress((void**)&x,    g_x);
    cudaGetSymbolAddress((void**)&qkv,  g_qkv);
    cudaGetSymbolAddress((void**)&ah,   g_ah);
    cudaGetSymbolAddress((void**)&al,   g_al);
    cudaGetSymbolAddress((void**)&fh,   g_fh);
    cudaGetSymbolAddress((void**)&fl,   g_fl);
    cudaGetSymbolAddress((void**)&wqkvh,g_wqkvh);
    cudaGetSymbolAddress((void**)&wqkvl,g_wqkvl);
    cudaGetSymbolAddress((void**)&woh,  g_woh);
    cudaGetSymbolAddress((void**)&wol,  g_wol);
    cudaGetSymbolAddress((void**)&w1h,  g_w1h);
    cudaGetSymbolAddress((void**)&w1l,  g_w1l);
    cudaGetSymbolAddress((void**)&w2h,  g_w2h);
    cudaGetSymbolAddress((void**)&w2l,  g_w2l);
    cudaGetSymbolAddress((void**)&wouth,g_wouth);
    cudaGetSymbolAddress((void**)&woutl,g_woutl);

    // Stream index 0: fused layer-0 QKV weight prep (one launch)
    {
        dim3 grid(DD / 32, DD / 32, 3);
        transpose_split_qkv_kernel<<<grid, 256>>>(Wq, Wk, Wv, wqkvh, wqkvl);
    }
    // Index 1: embedding
    embed_kernel<<<(MM*DD)/256, 256>>>(ctx, tok, pos, x);
    // Index 2: LN1 (layer 0)
    ln_split_kernel<<<MM, 256>>>(x, ln1s, ln1b, ah, al);
    // Index 3: layer-0 QKV GEMM  (harness offset +2 -> ncu global index 5)
    launch_gemm<0, false>(ah, al, wqkvh, wqkvl, nullptr, nullptr, qkv,
                          nullptr, nullptr, MM, QKVD, DD);

    // Remaining weight prep
    for (int l = 0; l < LL; l++) {
        size_t qo = (size_t)l * QKVD * DD;
        if (l > 0) {
            dim3 grid(DD / 32, DD / 32, 3);
            transpose_split_qkv_kernel<<<grid, 256>>>(
                Wq + (size_t)l*DD*DD, Wk + (size_t)l*DD*DD, Wv + (size_t)l*DD*DD,
                wqkvh + qo, wqkvl + qo);
        }
        launch_tsplit(Wo + (size_t)l*DD*DD,  woh + (size_t)l*DD*DD,  wol + (size_t)l*DD*DD,  DD, DD);
        launch_tsplit(W1 + (size_t)l*DD*DFF, w1h + (size_t)l*DFF*DD, w1l + (size_t)l*DFF*DD, DD, DFF);
        launch_tsplit(W2 + (size_t)l*DFF*DD, w2h + (size_t)l*DD*DFF, w2l + (size_t)l*DD*DFF, DFF, DD);
    }
    launch_tsplit(Wout, wouth, woutl, DD, VV);

    for (int l = 0; l < LL; l++) {
        const __nv_bfloat16* lwqh = wqkvh + (size_t)l*QKVD*DD;
        const __nv_bfloat16* lwql = wqkvl + (size_t)l*QKVD*DD;
        const __nv_bfloat16* lwoh = woh + (size_t)l*DD*DD;
        const __nv_bfloat16* lwol = wol + (size_t)l*DD*DD;
        const __nv_bfloat16* lw1h = w1h + (size_t)l*DFF*DD;
        const __nv_bfloat16* lw1l = w1l + (size_t)l*DFF*DD;
        const __nv_bfloat16* lw2h = w2h + (size_t)l*DD*DFF;
        const __nv_bfloat16* lw2l = w2l + (size_t)l*DD*DFF;

        if (l > 0) {
            ln_split_kernel<<<MM, 256>>>(x, ln1s + l*DD, ln1b + l*DD, ah, al);
            launch_gemm<0, false>(ah, al, lwqh, lwql, nullptr, nullptr, qkv,
                                  nullptr, nullptr, MM, QKVD, DD);
        }

        // attention -> ah/al (bf16 split)
        {
            dim3 grid(TT/128, HH, BB);
            attn_kernel<<<grid, 128>>>(qkv, ah, al);
        }

        // x = x + att @ Wo + bo
        launch_gemm<3, false>(ah, al, lwoh, lwol, bo + l*DD, x, x,
                              nullptr, nullptr, MM, DD, DD);

        // ah/al = split(LN2(x)); fh/fl = split(relu(ah @ W1 + b1))
        ln_split_kernel<<<MM, 256>>>(x, ln2s + l*DD, ln2b + l*DD, ah, al);
        launch_gemm<13, false>(ah, al, lw1h, lw1l, b1 + l*DFF, nullptr, nullptr,
                               fh, fl, MM, DFF, DD);

        // x = x + fh @ W2 + b2
        launch_gemm<3, false>(fh, fl, lw2h, lw2l, b2 + l*DD, x, x,
                              nullptr, nullptr, MM, DD, DFF);
    }

    // final LN + logits (M-fast rasterization: stream 131MB B once)
    ln_split_kernel<<<MM, 256>>>(x, lnfs, lnfb, ah, al);
    launch_gemm<1, true>(ah, al, wouth, woutl, bout, nullptr, out,
                         nullptr, nullptr, MM, VV, DD);
}

// round 13
// speedup vs baseline: 1.9852x; 1.0734x over previous
#include <cuda_runtime.h>
#include <cuda_bf16.h>
#include <math.h>
#include <stdint.h>

// Problem constants
#define BB   2
#define TT   2048
#define DD   1024
#define LL   4
#define HH   16
#define HD   64
#define VV   32000
#define DFF  4096
#define MM   (BB*TT)        // 4096 rows
#define QKVD 3072

// ---------------------------------------------------------------------------
// Scratch (device globals; allocation is forbidden). 256B aligned for bulk.
// Tiled bf16 layout everywhere: [row/128][k/32] tiles of 128 rows x 40 elems
// (32 data + 8 pad) = 5120 elems = 10240 B contiguous  ==  the smem image.
// NOTE: sizes written as (rows/128)*(K/32)*5120 to avoid int overflow.
// ---------------------------------------------------------------------------
__device__ __align__(256) float g_x  [MM*DD];
__device__ __align__(256) float g_qkv[MM*QKVD];

__device__ __align__(256) __nv_bfloat16 g_ah[(MM/128)*(DD/32)*5120],  g_al[(MM/128)*(DD/32)*5120];
__device__ __align__(256) __nv_bfloat16 g_fh[(MM/128)*(DFF/32)*5120], g_fl[(MM/128)*(DFF/32)*5120];

__device__ __align__(256) __nv_bfloat16 g_wqkvh[(QKVD/128)*(DD/32)*5120*LL], g_wqkvl[(QKVD/128)*(DD/32)*5120*LL];
__device__ __align__(256) __nv_bfloat16 g_woh  [(DD/128)*(DD/32)*5120*LL],   g_wol  [(DD/128)*(DD/32)*5120*LL];
__device__ __align__(256) __nv_bfloat16 g_w1h  [(DFF/128)*(DD/32)*5120*LL],  g_w1l  [(DFF/128)*(DD/32)*5120*LL];
__device__ __align__(256) __nv_bfloat16 g_w2h  [(DD/128)*(DFF/32)*5120*LL],  g_w2l  [(DD/128)*(DFF/32)*5120*LL];
__device__ __align__(256) __nv_bfloat16 g_wouth[(VV/128)*(DD/32)*5120],      g_woutl[(VV/128)*(DD/32)*5120];

// tiled offset: element index for (row, k) with K/32 chunks per row-tile
__device__ __forceinline__ size_t tiled_off(int row, int k, int kdiv32) {
    return ((size_t)(row >> 7) * kdiv32 + (k >> 5)) * 5120
         + (size_t)((row & 127) * 40 + (k & 31));
}

// ---------------------------------------------------------------------------
// PTX helpers (sm_90 base ISA; no 'a'-suffix features)
// ---------------------------------------------------------------------------
__device__ __forceinline__ uint32_t smem_u32(const void* p) {
    return (uint32_t)__cvta_generic_to_shared(p);
}
__device__ __forceinline__ void ldmat_x4(uint32_t* r, uint32_t addr) {
    asm volatile("ldmatrix.sync.aligned.m8n8.x4.shared.b16 {%0,%1,%2,%3}, [%4];"
                 : "=r"(r[0]), "=r"(r[1]), "=r"(r[2]), "=r"(r[3]) : "r"(addr));
}
__device__ __forceinline__ void mma16816(float* d, const uint32_t* a,
                                         const uint32_t* b) {
    asm volatile(
        "mma.sync.aligned.m16n8k16.row.col.f32.bf16.bf16.f32 "
        "{%0,%1,%2,%3}, {%4,%5,%6,%7}, {%8,%9}, {%0,%1,%2,%3};"
        : "+f"(d[0]), "+f"(d[1]), "+f"(d[2]), "+f"(d[3])
        : "r"(a[0]), "r"(a[1]), "r"(a[2]), "r"(a[3]), "r"(b[0]), "r"(b[1]));
}

#define MBAR_INIT(a, c) \
    asm volatile("mbarrier.init.shared.b64 [%0], %1;" :: "r"(a), "r"(c) : "memory")
#define MBAR_EXPECT(a, bytes) \
    asm volatile("mbarrier.arrive.expect_tx.shared.b64 _, [%0], %1;" \
                 :: "r"(a), "r"((uint32_t)(bytes)) : "memory")
#define CP_BULK(dst, src, bytes, mbar) \
    asm volatile("cp.async.bulk.shared::cta.global.mbarrier::complete_tx::bytes " \
                 "[%0], [%1], %2, [%3];" \
                 :: "r"(dst), "l"(src), "r"((uint32_t)(bytes)), "r"(mbar) : "memory")

__device__ __forceinline__ void mbar_wait(uint32_t mbar, int parity) {
    asm volatile(
        "{\n\t.reg .pred P;\n"
        "W%=:\n\t"
        "mbarrier.try_wait.parity.acquire.cta.shared::cta.b64 P, [%0], %1, 0x989680;\n\t"
        "@P bra D%=;\n\t"
        "bra W%=;\n"
        "D%=:\n\t}"
        :: "r"(mbar), "r"((uint32_t)parity) : "memory");
}

// ---------------------------------------------------------------------------
// Tensor GEMM: C[M,N] = (Ah+Al)[M,K] @ (Bh+Bl)[N,K]^T  (3xBF16 split)
// CTA tile 128x128, BK=32, 256 threads (2x4 warps, 64x32 warp tile),
// 2 CTAs/SM. Operands pre-tiled in gmem as 10240B smem images -> loaded with
// cp.async.bulk (4 bulk ops/chunk, 1 issuing thread) + mbarrier pipeline.
// MODE: bit0 +bias[n], bit1 +res[m,n], bit2 relu, bit3 write bf16 hi/lo split
// SWAPG: bm = blockIdx.x (M-fast rasterization; for huge-N logits GEMM)
// ---------------------------------------------------------------------------
#define TM 128
#define TN 128
#define BK 32
#define NTHR 256
#define SA 40
#define TILE_BYT 10240                       // one operand tile-chunk
#define STAGE_BYT (4*TILE_BYT)               // Ah,Al,Bh,Bl = 40960
#define GEMM_SMEM (2*STAGE_BYT + 64)         // + mbarriers

template<int MODE, bool SWAPG>
__global__ void __launch_bounds__(NTHR, 2) tc_gemm(
    int M, int N, int K,
    const __nv_bfloat16* __restrict__ Ah, const __nv_bfloat16* __restrict__ Al,
    const __nv_bfloat16* __restrict__ Bh, const __nv_bfloat16* __restrict__ Bl,
    const float* __restrict__ bias, const float* __restrict__ res,
    float* __restrict__ C, __nv_bfloat16* __restrict__ Ch,
    __nv_bfloat16* __restrict__ Cl)
{
    extern __shared__ __nv_bfloat16 sm[];
    uint32_t sbase = smem_u32(sm);
    uint32_t ctrl  = sbase + 2*STAGE_BYT;    // mbar0 @ +0, mbar1 @ +8
    int tid = threadIdx.x;
    int bm = SWAPG ? blockIdx.x : blockIdx.y;
    int bn = SWAPG ? blockIdx.y : blockIdx.x;
    int warp = tid >> 5, lane = tid & 31;
    int wm = warp & 1, wn = warp >> 1;       // warp grid 2 x 4, tile 64x32

    const int KC = K >> 5;                   // chunks
    const __nv_bfloat16* tAh = Ah + (size_t)bm * KC * 5120;
    const __nv_bfloat16* tAl = Al + (size_t)bm * KC * 5120;
    const __nv_bfloat16* tBh = Bh + (size_t)bn * KC * 5120;
    const __nv_bfloat16* tBl = Bl + (size_t)bn * KC * 5120;

    if (tid == 0) { MBAR_INIT(ctrl, 1); MBAR_INIT(ctrl + 8, 1); }
    __syncthreads();

    float acc[4][4][4];
    #pragma unroll
    for (int i = 0; i < 4; i++)
        #pragma unroll
        for (int j = 0; j < 4; j++)
            #pragma unroll
            for (int u = 0; u < 4; u++) acc[i][j][u] = 0.f;

    int mat = lane >> 3;
    int row_off = (mat & 1) * 8 + (lane & 7);
    int kblk_off = (mat >> 1) * 8;

    // prologue: chunk 0 -> stage 0
    if (tid == 0) {
        MBAR_EXPECT(ctrl, STAGE_BYT);
        uint32_t sb = sbase;
        CP_BULK(sb,              (const void*)(tAh), TILE_BYT, ctrl);
        CP_BULK(sb +   TILE_BYT, (const void*)(tAl), TILE_BYT, ctrl);
        CP_BULK(sb + 2*TILE_BYT, (const void*)(tBh), TILE_BYT, ctrl);
        CP_BULK(sb + 3*TILE_BYT, (const void*)(tBl), TILE_BYT, ctrl);
    }

    int ph[2] = {0, 0};
    for (int c = 0; c < KC; c++) {
        int s = c & 1;
        if (c + 1 < KC && tid == 0) {
            uint32_t mb = ctrl + (uint32_t)((s ^ 1) * 8);
            MBAR_EXPECT(mb, STAGE_BYT);
            uint32_t sb = sbase + (uint32_t)((s ^ 1) * STAGE_BYT);
            size_t go = (size_t)(c + 1) * 5120;
            CP_BULK(sb,              (const void*)(tAh + go), TILE_BYT, mb);
            CP_BULK(sb +   TILE_BYT, (const void*)(tAl + go), TILE_BYT, mb);
            CP_BULK(sb + 2*TILE_BYT, (const void*)(tBh + go), TILE_BYT, mb);
            CP_BULK(sb + 3*TILE_BYT, (const void*)(tBl + go), TILE_BYT, mb);
        }
        mbar_wait(ctrl + (uint32_t)(s * 8), ph[s]);
        ph[s] ^= 1;

        uint32_t stg = sbase + (uint32_t)(s * STAGE_BYT);
        uint32_t Ash = stg, Asl = stg + TILE_BYT;
        uint32_t Bsh = stg + 2*TILE_BYT, Bsl = stg + 3*TILE_BYT;

        #pragma unroll
        for (int ks = 0; ks < 2; ks++) {
            int k0 = ks * 16 + kblk_off;
            uint32_t af[4][4], bf[2][4];
            // pass 0: Ah * Bh
            #pragma unroll
            for (int mt = 0; mt < 4; mt++) {
                int r = wm * 64 + mt * 16 + row_off;
                ldmat_x4(af[mt], Ash + (uint32_t)((r * SA + k0) * 2));
            }
            #pragma unroll
            for (int ng = 0; ng < 2; ng++) {
                int r = wn * 32 + ng * 16 + row_off;
                ldmat_x4(bf[ng], Bsh + (uint32_t)((r * SA + k0) * 2));
            }
            #pragma unroll
            for (int mt = 0; mt < 4; mt++)
                #pragma unroll
                for (int nt = 0; nt < 4; nt++) {
                    uint32_t bb[2] = { bf[nt >> 1][nt & 1],
                                       bf[nt >> 1][2 + (nt & 1)] };
                    mma16816(acc[mt][nt], af[mt], bb);
                }
            // pass 1: Ah * Bl (af stays live)
            #pragma unroll
            for (int ng = 0; ng < 2; ng++) {
                int r = wn * 32 + ng * 16 + row_off;
                ldmat_x4(bf[ng], Bsl + (uint32_t)((r * SA + k0) * 2));
            }
            #pragma unroll
            for (int mt = 0; mt < 4; mt++)
                #pragma unroll
                for (int nt = 0; nt < 4; nt++) {
                    uint32_t bb[2] = { bf[nt >> 1][nt & 1],
                                       bf[nt >> 1][2 + (nt & 1)] };
                    mma16816(acc[mt][nt], af[mt], bb);
                }
            // pass 2: Al * Bh
            #pragma unroll
            for (int mt = 0; mt < 4; mt++) {
                int r = wm * 64 + mt * 16 + row_off;
                ldmat_x4(af[mt], Asl + (uint32_t)((r * SA + k0) * 2));
            }
            #pragma unroll
            for (int ng = 0; ng < 2; ng++) {
                int r = wn * 32 + ng * 16 + row_off;
                ldmat_x4(bf[ng], Bsh + (uint32_t)((r * SA + k0) * 2));
            }
            #pragma unroll
            for (int mt = 0; mt < 4; mt++)
                #pragma unroll
                for (int nt = 0; nt < 4; nt++) {
                    uint32_t bb[2] = { bf[nt >> 1][nt & 1],
                                       bf[nt >> 1][2 + (nt & 1)] };
                    mma16816(acc[mt][nt], af[mt], bb);
                }
        }
        __syncthreads();   // all consumers done with stage s before reuse
    }

    // epilogue (compile-time MODE)
    int qr = lane >> 2, qc = (lane & 3) * 2;
    #pragma unroll
    for (int mt = 0; mt < 4; mt++) {
        #pragma unroll
        for (int half = 0; half < 2; half++) {
            int grow = bm * TM + wm * 64 + mt * 16 + half * 8 + qr;
            size_t rowo = (size_t)grow * N;
            #pragma unroll
            for (int nt = 0; nt < 4; nt++) {
                int gcol = bn * TN + wn * 32 + nt * 8 + qc;
                float v0 = acc[mt][nt][half * 2 + 0];
                float v1 = acc[mt][nt][half * 2 + 1];
                if (MODE & 1) { v0 += bias[gcol]; v1 += bias[gcol + 1]; }
                if (MODE & 2) {
                    const float2 r2 = *(const float2*)(res + rowo + gcol);
                    v0 += r2.x; v1 += r2.y;
                }
                if (MODE & 4) { v0 = fmaxf(v0, 0.f); v1 = fmaxf(v1, 0.f); }
                if (MODE & 8) {
                    // tiled bf16 hi/lo output (A-side image for next GEMM)
                    size_t o = tiled_off(grow, gcol, N >> 5);
                    __nv_bfloat16 h0 = __float2bfloat16(v0);
                    __nv_bfloat16 h1 = __float2bfloat16(v1);
                    __nv_bfloat162 hp; hp.x = h0; hp.y = h1;
                    __nv_bfloat162 lp;
                    lp.x = __float2bfloat16(v0 - __bfloat162float(h0));
                    lp.y = __float2bfloat16(v1 - __bfloat162float(h1));
                    *(__nv_bfloat162*)(Ch + o) = hp;
                    *(__nv_bfloat162*)(Cl + o) = lp;
                } else {
                    float2 o2; o2.x = v0; o2.y = v1;
                    *(float2*)(C + rowo + gcol) = o2;
                }
            }
        }
    }
}

// ---------------------------------------------------------------------------
// Weight transpose + split: W[K,N] fp32 -> tiled bf16 hi/lo images
// ---------------------------------------------------------------------------
__device__ __forceinline__ void tsplit_body(
    const float* __restrict__ W, __nv_bfloat16* __restrict__ Bh,
    __nv_bfloat16* __restrict__ Bl, int K, int N, float (*t)[33])
{
    int n0 = blockIdx.x * 32, k0 = blockIdx.y * 32;
    int tx = threadIdx.x & 31, ty = threadIdx.x >> 5;   // ty 0..7
    #pragma unroll
    for (int i = 0; i < 32; i += 8)
        t[ty + i][tx] = W[(size_t)(k0 + ty + i) * N + n0 + tx];
    __syncthreads();
    int kdiv32 = K >> 5;
    #pragma unroll
    for (int i = 0; i < 32; i += 8) {
        float v = t[tx][ty + i];
        __nv_bfloat16 hi = __float2bfloat16(v);
        size_t o = tiled_off(n0 + ty + i, k0 + tx, kdiv32);
        Bh[o] = hi;
        Bl[o] = __float2bfloat16(v - __bfloat162float(hi));
    }
}

__global__ __launch_bounds__(256) void transpose_split_kernel(
    const float* __restrict__ W, __nv_bfloat16* __restrict__ Bh,
    __nv_bfloat16* __restrict__ Bl, int K, int N)
{
    __shared__ float t[32][33];
    tsplit_body(W, Bh, Bl, K, N, t);
}

__global__ __launch_bounds__(256) void transpose_split_qkv_kernel(
    const float* __restrict__ Wq, const float* __restrict__ Wk,
    const float* __restrict__ Wv, __nv_bfloat16* __restrict__ Bh,
    __nv_bfloat16* __restrict__ Bl)
{
    __shared__ float t[32][33];
    int z = blockIdx.z;
    const float* W = (z == 0) ? Wq : (z == 1) ? Wk : Wv;
    size_t off = (size_t)z * (DD/128) * (DD/32) * 5120;  // = DD*DD*1.25
    tsplit_body(W, Bh + off, Bl + off, DD, DD, t);
}

// ---------------------------------------------------------------------------
// Embedding
// ---------------------------------------------------------------------------
__global__ __launch_bounds__(256) void embed_kernel(
    const int* __restrict__ ctx, const float* __restrict__ tok,
    const float* __restrict__ pos, float* __restrict__ x)
{
    int idx = blockIdx.x * 256 + threadIdx.x;
    int d  = idx & (DD - 1);
    int bt = idx >> 10;
    int t  = bt & (TT - 1);
    int v  = ctx[bt];
    x[idx] = tok[(size_t)v * DD + d] + pos[(size_t)t * DD + d];
}

// ---------------------------------------------------------------------------
// LayerNorm fused with tiled bf16 hi/lo split output
// ---------------------------------------------------------------------------
__global__ __launch_bounds__(256) void ln_split_kernel(
    const float* __restrict__ x, const float* __restrict__ s,
    const float* __restrict__ b, __nv_bfloat16* __restrict__ yh,
    __nv_bfloat16* __restrict__ yl)
{
    int row = blockIdx.x;
    const float* xr = x + (size_t)row * DD;
    int tid = threadIdx.x;

    float v0 = xr[tid], v1 = xr[tid+256], v2 = xr[tid+512], v3 = xr[tid+768];
    float sum = v0+v1+v2+v3;
    float sq  = v0*v0+v1*v1+v2*v2+v3*v3;
    #pragma unroll
    for (int o = 16; o > 0; o >>= 1) {
        sum += __shfl_xor_sync(0xFFFFFFFFu, sum, o);
        sq  += __shfl_xor_sync(0xFFFFFFFFu, sq,  o);
    }
    __shared__ float ssum[8], ssq[8], red[2];
    if ((tid & 31) == 0) { ssum[tid>>5] = sum; ssq[tid>>5] = sq; }
    __syncthreads();
    if (tid < 32) {
        float a = (tid < 8) ? ssum[tid] : 0.f;
        float c = (tid < 8) ? ssq[tid]  : 0.f;
        #pragma unroll
        for (int o = 4; o > 0; o >>= 1) {
            a += __shfl_xor_sync(0xFFFFFFFFu, a, o);
            c += __shfl_xor_sync(0xFFFFFFFFu, c, o);
        }
        if (tid == 0) { red[0] = a; red[1] = c; }
    }
    __syncthreads();
    float mean = red[0] * (1.f/DD);
    float var  = red[1] * (1.f/DD) - mean*mean;
    float inv  = rsqrtf(var + 1e-5f);
    #pragma unroll
    for (int i = 0; i < 4; i++) {
        int c = tid + i*256;
        float val = (xr[c] - mean) * inv * s[c] + b[c];
        __nv_bfloat16 hi = __float2bfloat16(val);
        size_t o = tiled_off(row, c, DD >> 5);
        yh[o] = hi;
        yl[o] = __float2bfloat16(val - __bfloat162float(hi));
    }
}

// ---------------------------------------------------------------------------
// Flash attention (causal), QKV packed [M,3072]; tiled bf16 hi/lo output
// ---------------------------------------------------------------------------
__global__ __launch_bounds__(128) void attn_kernel(
    const float* __restrict__ QKV, __nv_bfloat16* __restrict__ Oh,
    __nv_bfloat16* __restrict__ Ol)
{
    int qt = blockIdx.x, h = blockIdx.y, b = blockIdx.z;
    int tid = threadIdx.x;
    int q_idx = qt * 128 + tid;

    const float* qp = QKV + ((size_t)(b*TT) + q_idx) * QKVD + h * HD;

    float qr[64];
    #pragma unroll
    for (int c = 0; c < 16; c++) {
        float4 t4 = *(const float4*)(qp + c*4);
        qr[4*c+0] = t4.x * 0.125f; qr[4*c+1] = t4.y * 0.125f;
        qr[4*c+2] = t4.z * 0.125f; qr[4*c+3] = t4.w * 0.125f;
    }
    float ob[64];
    #pragma unroll
    for (int d = 0; d < 64; d++) ob[d] = 0.f;
    float m = -1e30f, lsum = 0.f;

    __shared__ float4 Ks[16][16];
    __shared__ float4 Vs[16][16];

    int kend = qt * 128 + 128;
    for (int k0 = 0; k0 < kend; k0 += 16) {
        __syncthreads();
        #pragma unroll
        for (int i = 0; i < 2; i++) {
            int idx = tid + i*128;
            int r = idx >> 4, c = idx & 15;
            size_t rb = ((size_t)(b*TT) + k0 + r) * QKVD + h * HD + c*4;
            Ks[r][c] = *(const float4*)(QKV + rb + DD);
            Vs[r][c] = *(const float4*)(QKV + rb + 2*DD);
        }
        __syncthreads();

        float s[16];
        #pragma unroll
        for (int j = 0; j < 16; j++) {
            float acc = 0.f;
            #pragma unroll
            for (int c = 0; c < 16; c++) {
                float4 kk = Ks[j][c];
                acc += qr[4*c+0]*kk.x + qr[4*c+1]*kk.y
                     + qr[4*c+2]*kk.z + qr[4*c+3]*kk.w;
            }
            s[j] = (k0 + j <= q_idx) ? acc : -1e30f;
        }
        float mt = m;
        #pragma unroll
        for (int j = 0; j < 16; j++) mt = fmaxf(mt, s[j]);
        float corr = __expf(m - mt);
        m = mt;
        lsum *= corr;
        #pragma unroll
        for (int d = 0; d < 64; d++) ob[d] *= corr;

        #pragma unroll
        for (int j = 0; j < 16; j++) {
            float p = __expf(s[j] - m);
            lsum += p;
            #pragma unroll
            for (int c = 0; c < 16; c++) {
                float4 vv = Vs[j][c];
                ob[4*c+0] += p * vv.x; ob[4*c+1] += p * vv.y;
                ob[4*c+2] += p * vv.z; ob[4*c+3] += p * vv.w;
            }
        }
    }

    float inv = 1.f / lsum;
    int row = b*TT + q_idx;
    #pragma unroll
    for (int c = 0; c < 32; c++) {
        float u0 = ob[2*c+0]*inv, u1 = ob[2*c+1]*inv;
        int k = h * HD + 2*c;
        size_t o = tiled_off(row, k, DD >> 5);
        __nv_bfloat16 h0 = __float2bfloat16(u0);
        __nv_bfloat16 h1 = __float2bfloat16(u1);
        __nv_bfloat162 hp; hp.x = h0; hp.y = h1;
        __nv_bfloat162 lp;
        lp.x = __float2bfloat16(u0 - __bfloat162float(h0));
        lp.y = __float2bfloat16(u1 - __bfloat162float(h1));
        *(__nv_bfloat162*)(Oh + o) = hp;
        *(__nv_bfloat162*)(Ol + o) = lp;
    }
}

// ---------------------------------------------------------------------------
// Host orchestration
// ---------------------------------------------------------------------------
template<int MODE, bool SWAPG>
static void launch_gemm(const __nv_bfloat16* Ah, const __nv_bfloat16* Al,
                        const __nv_bfloat16* Bh, const __nv_bfloat16* Bl,
                        const float* bias, const float* res, float* C,
                        __nv_bfloat16* Ch, __nv_bfloat16* Cl,
                        int M, int N, int K)
{
    dim3 grid = SWAPG ? dim3(M / TM, N / TN) : dim3(N / TN, M / TM);
    tc_gemm<MODE, SWAPG><<<grid, NTHR, GEMM_SMEM>>>(M, N, K, Ah, Al, Bh, Bl,
                                                    bias, res, C, Ch, Cl);
}

static void launch_tsplit(const float* W, __nv_bfloat16* Bh, __nv_bfloat16* Bl,
                          int K, int N)
{
    dim3 grid(N / 32, K / 32);
    transpose_split_kernel<<<grid, 256>>>(W, Bh, Bl, K, N);
}

extern "C" void kernel_launch(void* const* d_in, const int* in_sizes, int n_in,
                              void* d_out, int out_size)
{
    const int*   ctx  = (const int*)  d_in[0];
    const float* tok  = (const float*)d_in[1];
    const float* pos  = (const float*)d_in[2];
    const float* Wq   = (const float*)d_in[3];
    const float* Wk   = (const float*)d_in[4];
    const float* Wv   = (const float*)d_in[5];
    const float* Wo   = (const float*)d_in[6];
    const float* bo   = (const float*)d_in[7];
    const float* ln1s = (const float*)d_in[8];
    const float* ln1b = (const float*)d_in[9];
    const float* W1   = (const float*)d_in[10];
    const float* b1   = (const float*)d_in[11];
    const float* W2   = (const float*)d_in[12];
    const float* b2   = (const float*)d_in[13];
    const float* ln2s = (const float*)d_in[14];
    const float* ln2b = (const float*)d_in[15];
    const float* lnfs = (const float*)d_in[16];
    const float* lnfb = (const float*)d_in[17];
    const float* Wout = (const float*)d_in[18];
    const float* bout = (const float*)d_in[19];
    float* out = (float*)d_out;

    cudaFuncSetAttribute(tc_gemm<0,false>,  cudaFuncAttributeMaxDynamicSharedMemorySize, GEMM_SMEM);
    cudaFuncSetAttribute(tc_gemm<3,false>,  cudaFuncAttributeMaxDynamicSharedMemorySize, GEMM_SMEM);
    cudaFuncSetAttribute(tc_gemm<13,false>, cudaFuncAttributeMaxDynamicSharedMemorySize, GEMM_SMEM);
    cudaFuncSetAttribute(tc_gemm<1,true>,   cudaFuncAttributeMaxDynamicSharedMemorySize, GEMM_SMEM);

    float *x, *qkv;
    __nv_bfloat16 *ah, *al, *fh, *fl;
    __nv_bfloat16 *wqkvh, *wqkvl, *woh, *wol, *w1h, *w1l, *w2h, *w2l, *wouth, *woutl;
    cudaGetSymbolAddress((void**)&x,    g_x);
    cudaGetSymbolAddress((void**)&qkv,  g_qkv);
    cudaGetSymbolAddress((void**)&ah,   g_ah);
    cudaGetSymbolAddress((void**)&al,   g_al);
    cudaGetSymbolAddress((void**)&fh,   g_fh);
    cudaGetSymbolAddress((void**)&fl,   g_fl);
    cudaGetSymbolAddress((void**)&wqkvh,g_wqkvh);
    cudaGetSymbolAddress((void**)&wqkvl,g_wqkvl);
    cudaGetSymbolAddress((void**)&woh,  g_woh);
    cudaGetSymbolAddress((void**)&wol,  g_wol);
    cudaGetSymbolAddress((void**)&w1h,  g_w1h);
    cudaGetSymbolAddress((void**)&w1l,  g_w1l);
    cudaGetSymbolAddress((void**)&w2h,  g_w2h);
    cudaGetSymbolAddress((void**)&w2l,  g_w2l);
    cudaGetSymbolAddress((void**)&wouth,g_wouth);
    cudaGetSymbolAddress((void**)&woutl,g_woutl);

    const size_t WQKV_L = (size_t)(QKVD/128)*(DD/32)*5120;
    const size_t WDD_L  = (size_t)(DD/128)*(DD/32)*5120;
    const size_t W1_L   = (size_t)(DFF/128)*(DD/32)*5120;
    const size_t W2_L   = (size_t)(DD/128)*(DFF/32)*5120;

    // Stream index 0: fused layer-0 QKV weight prep
    {
        dim3 grid(DD / 32, DD / 32, 3);
        transpose_split_qkv_kernel<<<grid, 256>>>(Wq, Wk, Wv, wqkvh, wqkvl);
    }
    // Index 1: embedding
    embed_kernel<<<(MM*DD)/256, 256>>>(ctx, tok, pos, x);
    // Index 2: LN1 (layer 0)
    ln_split_kernel<<<MM, 256>>>(x, ln1s, ln1b, ah, al);
    // Index 3: layer-0 QKV GEMM  (-> ncu global index 5)
    launch_gemm<0, false>(ah, al, wqkvh, wqkvl, nullptr, nullptr, qkv,
                          nullptr, nullptr, MM, QKVD, DD);

    // Remaining weight prep
    for (int l = 0; l < LL; l++) {
        if (l > 0) {
            dim3 grid(DD / 32, DD / 32, 3);
            transpose_split_qkv_kernel<<<grid, 256>>>(
                Wq + (size_t)l*DD*DD, Wk + (size_t)l*DD*DD, Wv + (size_t)l*DD*DD,
                wqkvh + (size_t)l*WQKV_L, wqkvl + (size_t)l*WQKV_L);
        }
        launch_tsplit(Wo + (size_t)l*DD*DD,  woh + (size_t)l*WDD_L, wol + (size_t)l*WDD_L, DD, DD);
        launch_tsplit(W1 + (size_t)l*DD*DFF, w1h + (size_t)l*W1_L,  w1l + (size_t)l*W1_L,  DD, DFF);
        launch_tsplit(W2 + (size_t)l*DFF*DD, w2h + (size_t)l*W2_L,  w2l + (size_t)l*W2_L,  DFF, DD);
    }
    launch_tsplit(Wout, wouth, woutl, DD, VV);

    for (int l = 0; l < LL; l++) {
        const __nv_bfloat16* lwqh = wqkvh + (size_t)l*WQKV_L;
        const __nv_bfloat16* lwql = wqkvl + (size_t)l*WQKV_L;
        const __nv_bfloat16* lwoh = woh + (size_t)l*WDD_L;
        const __nv_bfloat16* lwol = wol + (size_t)l*WDD_L;
        const __nv_bfloat16* lw1h = w1h + (size_t)l*W1_L;
        const __nv_bfloat16* lw1l = w1l + (size_t)l*W1_L;
        const __nv_bfloat16* lw2h = w2h + (size_t)l*W2_L;
        const __nv_bfloat16* lw2l = w2l + (size_t)l*W2_L;

        if (l > 0) {
            ln_split_kernel<<<MM, 256>>>(x, ln1s + l*DD, ln1b + l*DD, ah, al);
            launch_gemm<0, false>(ah, al, lwqh, lwql, nullptr, nullptr, qkv,
                                  nullptr, nullptr, MM, QKVD, DD);
        }

        // attention -> ah/al (tiled bf16 split)
        {
            dim3 grid(TT/128, HH, BB);
            attn_kernel<<<grid, 128>>>(qkv, ah, al);
        }

        // x = x + att @ Wo + bo
        launch_gemm<3, false>(ah, al, lwoh, lwol, bo + l*DD, x, x,
                              nullptr, nullptr, MM, DD, DD);

        // ah/al = split(LN2(x)); fh/fl = split(relu(ah @ W1 + b1))
        ln_split_kernel<<<MM, 256>>>(x, ln2s + l*DD, ln2b + l*DD, ah, al);
        launch_gemm<13, false>(ah, al, lw1h, lw1l, b1 + l*DFF, nullptr, nullptr,
                               fh, fl, MM, DFF, DD);

        // x = x + fh @ W2 + b2
        launch_gemm<3, false>(fh, fl, lw2h, lw2l, b2 + l*DD, x, x,
                              nullptr, nullptr, MM, DD, DFF);
    }

    // final LN + logits (M-fast rasterization: stream 131MB B once)
    ln_split_kernel<<<MM, 256>>>(x, lnfs, lnfb, ah, al);
    launch_gemm<1, true>(ah, al, wouth, woutl, bout, nullptr, out,
                         nullptr, nullptr, MM, VV, DD);
}